// round 7
// baseline (speedup 1.0000x reference)
#include <cuda_runtime.h>
#include <cuda_bf16.h>

#define BB   4
#define NQ   4096
#define MKV  512
#define DIM  1152
#define NH   16
#define HD   72
#define KCLD 73

// -------- scratch (static device globals; no allocation) --------
__device__ float          g_q32 [(size_t)BB*NQ*DIM];
__device__ float          g_kv32[(size_t)BB*MKV*2*DIM];
__device__ __nv_bfloat16  g_q16 [(size_t)BB*NQ*NH*HD];
__device__ __nv_bfloat16  g_k16 [(size_t)BB*NH*MKV*HD];
__device__ __nv_bfloat16  g_v16 [(size_t)BB*NH*MKV*HD];
__device__ float          g_att [(size_t)BB*NQ*DIM];

// ============================================================================
// Exact FP32 GEMM, SGEMM-order: C[M,N] = A[M,K] @ B[K,N] (+bias).
// Each C element is ONE ascending-k FFMA chain in a register — bit-identical
// to cuBLAS SGEMM's per-thread accumulation order.
// 256 threads, block tile 128x128, kc=16, per-thread 8x8 micro-tile.
// ============================================================================
#define KC  16
#define SLD 132

__global__ void __launch_bounds__(256) gemm_f32(
    const float* __restrict__ A, const float* __restrict__ B,
    const float* __restrict__ bias, float* __restrict__ C,
    int M, int N, int K)
{
    __shared__ float As[KC][SLD];   // transposed: As[k][m]
    __shared__ float Bs[KC][SLD];   // Bs[k][n]

    const int tid = threadIdx.x;
    const int tx  = tid & 15;        // 0..15 col group
    const int ty  = tid >> 4;        // 0..15 row group
    const int m0  = blockIdx.y * 128;
    const int n0  = blockIdx.x * 128;

    float acc[8][8];
    #pragma unroll
    for (int i = 0; i < 8; ++i)
        #pragma unroll
        for (int j = 0; j < 8; ++j) acc[i][j] = 0.0f;

    for (int kt = 0; kt < K; kt += KC) {
        // stage A tile 128x16 (transpose into As[k][m])
        #pragma unroll
        for (int i = tid; i < 512; i += 256) {
            int r = i >> 2, c4 = (i & 3) * 4;
            float4 v = *(const float4*)&A[(size_t)(m0 + r) * K + kt + c4];
            As[c4 + 0][r] = v.x;
            As[c4 + 1][r] = v.y;
            As[c4 + 2][r] = v.z;
            As[c4 + 3][r] = v.w;
        }
        // stage B tile 16x128
        #pragma unroll
        for (int i = tid; i < 512; i += 256) {
            int r = i >> 5, c4 = (i & 31) * 4;
            float4 v = *(const float4*)&B[(size_t)(kt + r) * N + n0 + c4];
            *(float4*)&Bs[r][c4] = v;
        }
        __syncthreads();

        #pragma unroll
        for (int kk = 0; kk < KC; ++kk) {
            float a[8], b[8];
            *(float4*)(a)     = *(const float4*)&As[kk][ty * 8];
            *(float4*)(a + 4) = *(const float4*)&As[kk][ty * 8 + 4];
            *(float4*)(b)     = *(const float4*)&Bs[kk][tx * 8];
            *(float4*)(b + 4) = *(const float4*)&Bs[kk][tx * 8 + 4];
            #pragma unroll
            for (int i = 0; i < 8; ++i)
                #pragma unroll
                for (int j = 0; j < 8; ++j)
                    acc[i][j] = fmaf(a[i], b[j], acc[i][j]);
        }
        __syncthreads();
    }

    // epilogue: optional bias (single fp32 add, matching (x@w)+b), float4 stores
    #pragma unroll
    for (int i = 0; i < 8; ++i) {
        const size_t gm = m0 + ty * 8 + i;
        const int    gn = n0 + tx * 8;
        float o[8];
        #pragma unroll
        for (int j = 0; j < 8; ++j)
            o[j] = bias ? (acc[i][j] + bias[gn + j]) : acc[i][j];
        *(float4*)&C[gm * N + gn]     = *(float4*)(o);
        *(float4*)&C[gm * N + gn + 4] = *(float4*)(o + 4);
    }
}

// ============================================================================
// Q path: bias + RMSNorm + bf16 cast. One warp per (b,n,h).
// ============================================================================
__global__ void __launch_bounds__(256) rms_q_kernel(
    const float* __restrict__ q32, const float* __restrict__ qb,
    const float* __restrict__ qw, __nv_bfloat16* __restrict__ q16)
{
    const int wid  = threadIdx.x >> 5;
    const int lane = threadIdx.x & 31;
    const size_t row = (size_t)blockIdx.x * 8 + wid;
    const int h = (int)(row % NH);
    const float* src = q32 + row * HD;

    float v0 = src[lane]      + qb[h * HD + lane];
    float v1 = src[lane + 32] + qb[h * HD + lane + 32];
    float v2 = (lane < 8) ? src[lane + 64] + qb[h * HD + lane + 64] : 0.0f;

    float ss = v0 * v0 + v1 * v1 + v2 * v2;
    #pragma unroll
    for (int o = 16; o; o >>= 1) ss += __shfl_xor_sync(0xffffffffu, ss, o);
    const float inv = 1.0f / sqrtf(ss * (1.0f / 72.0f) + 1e-6f);

    __nv_bfloat16* dst = q16 + row * HD;
    dst[lane]      = __float2bfloat16(v0 * inv * qw[lane]);
    dst[lane + 32] = __float2bfloat16(v1 * inv * qw[lane + 32]);
    if (lane < 8)
        dst[lane + 64] = __float2bfloat16(v2 * inv * qw[lane + 64]);
}

// ============================================================================
// KV path: bias + RMSNorm(k) + cast(v), transpose to [b][h][m][d].
// ============================================================================
__global__ void __launch_bounds__(256) rms_kv_kernel(
    const float* __restrict__ kv32, const float* __restrict__ kvb,
    const float* __restrict__ knw,
    __nv_bfloat16* __restrict__ k16, __nv_bfloat16* __restrict__ v16)
{
    const int wid  = threadIdx.x >> 5;
    const int lane = threadIdx.x & 31;
    const int rid  = blockIdx.x * 8 + wid;
    const int b = rid / (MKV * NH);
    const int m = (rid / NH) % MKV;
    const int h = rid % NH;

    const size_t base = ((size_t)(b * MKV + m) * 2) * DIM + h * HD;
    const float* ksrc = kv32 + base;
    const float* vsrc = kv32 + base + DIM;
    const float* kb   = kvb + h * HD;
    const float* vb   = kvb + DIM + h * HD;
    const size_t obase = ((size_t)(b * NH + h) * MKV + m) * HD;

    float k0 = ksrc[lane]      + kb[lane];
    float k1 = ksrc[lane + 32] + kb[lane + 32];
    float k2 = (lane < 8) ? ksrc[lane + 64] + kb[lane + 64] : 0.0f;
    float ss = k0 * k0 + k1 * k1 + k2 * k2;
    #pragma unroll
    for (int o = 16; o; o >>= 1) ss += __shfl_xor_sync(0xffffffffu, ss, o);
    const float inv = 1.0f / sqrtf(ss * (1.0f / 72.0f) + 1e-6f);
    k16[obase + lane]      = __float2bfloat16(k0 * inv * knw[lane]);
    k16[obase + lane + 32] = __float2bfloat16(k1 * inv * knw[lane + 32]);
    if (lane < 8)
        k16[obase + lane + 64] = __float2bfloat16(k2 * inv * knw[lane + 64]);

    v16[obase + lane]      = __float2bfloat16(vsrc[lane]      + vb[lane]);
    v16[obase + lane + 32] = __float2bfloat16(vsrc[lane + 32] + vb[lane + 32]);
    if (lane < 8)
        v16[obase + lane + 64] = __float2bfloat16(vsrc[lane + 64] + vb[lane + 64]);
}

// ============================================================================
// EXACT SCALAR ATTENTION (frozen — arithmetic proven in R4/R5).
// ============================================================================
#define SMEM_SCALAR ((32*KCLD + 128*KCLD + 32*MKV) * 4 + 32*MKV*2)

__global__ void __launch_bounds__(256) attn_scalar(
    const __nv_bfloat16* __restrict__ q16, const __nv_bfloat16* __restrict__ k16,
    const __nv_bfloat16* __restrict__ v16, const int* __restrict__ kvlen_p,
    float* __restrict__ out)
{
    extern __shared__ char smem[];
    float* qf = (float*)smem;                            // [32][73]
    float* kc = qf + 32 * KCLD;                          // [128][73]
    float* sc = kc + 128 * KCLD;                         // [32][512]
    __nv_bfloat16* pb = (__nv_bfloat16*)(sc + 32 * MKV); // [32][512]

    const int tid  = threadIdx.x;
    const int wid  = tid >> 5;
    const int lane = tid & 31;
    const int n0 = blockIdx.x * 32;
    const int h  = blockIdx.y;
    const int b  = blockIdx.z;
    const int kvlen = kvlen_p[b];
    const int nchunks = (kvlen + 127) >> 7;
    const float scale = 0.11785113019775793f;   // 1/sqrt(72)

    const size_t qbase = (((size_t)(b * NQ + n0)) * NH + h) * HD;
    for (int i = tid; i < 32 * HD; i += 256) {
        int r = i / HD, c = i % HD;
        qf[r * KCLD + c] = __bfloat162float(q16[qbase + (size_t)r * NH * HD + c]);
    }

    const size_t kvbase = ((size_t)(b * NH + h)) * MKV * HD;

    // ---------- Phase 1: scores ----------
    for (int mc = 0; mc < nchunks; ++mc) {
        __syncthreads();
        for (int i = tid; i < 128 * HD; i += 256) {
            int r = i / HD, c = i % HD;
            kc[r * KCLD + c] =
                __bfloat162float(k16[kvbase + (size_t)(mc * 128 + r) * HD + c]);
        }
        __syncthreads();
        for (int i = wid; i < 32; i += 8) {
            const float* qr = qf + i * KCLD;
            #pragma unroll
            for (int jc = 0; jc < 4; ++jc) {
                const int j = jc * 32 + lane;
                const float* kr = kc + j * KCLD;
                float acc = 0.0f;
                #pragma unroll
                for (int d = 0; d < HD; ++d)
                    acc = fmaf(qr[d], kr[d], acc);
                sc[i * MKV + mc * 128 + j] = acc * scale;
            }
        }
    }
    __syncthreads();

    // ---------- Phase 2: masked softmax ----------
    for (int i = wid; i < 32; i += 8) {
        float* row = sc + i * MKV;
        float mx = -1e30f;
        for (int j = lane; j < kvlen; j += 32) mx = fmaxf(mx, row[j]);
        #pragma unroll
        for (int o = 16; o; o >>= 1) mx = fmaxf(mx, __shfl_xor_sync(0xffffffffu, mx, o));
        float sum = 0.0f;
        for (int j = lane; j < kvlen; j += 32) {
            float e = expf(row[j] - mx);
            row[j] = e; sum += e;
        }
        #pragma unroll
        for (int o = 16; o; o >>= 1) sum += __shfl_xor_sync(0xffffffffu, sum, o);
        for (int j = lane; j < kvlen; j += 32)
            pb[i * MKV + j] = __float2bfloat16(row[j] / sum);
    }

    // ---------- Phase 3: PV ----------
    float a0[4] = {0,0,0,0}, a1[4] = {0,0,0,0}, a2[4] = {0,0,0,0};
    for (int mc = 0; mc < nchunks; ++mc) {
        __syncthreads();
        for (int i = tid; i < 128 * HD; i += 256) {
            int r = i / HD, c = i % HD;
            kc[r * KCLD + c] =
                __bfloat162float(v16[kvbase + (size_t)(mc * 128 + r) * HD + c]);
        }
        __syncthreads();
        const int mmax = min(128, kvlen - mc * 128);
        #pragma unroll
        for (int t = 0; t < 4; ++t) {
            const int i = wid + 8 * t;
            const __nv_bfloat16* prow = pb + i * MKV + mc * 128;
            for (int mm = 0; mm < mmax; ++mm) {
                const float p = __bfloat162float(prow[mm]);
                const float* vr = kc + mm * KCLD;
                a0[t] = fmaf(p, vr[lane], a0[t]);
                a1[t] = fmaf(p, vr[lane + 32], a1[t]);
                if (lane < 8) a2[t] = fmaf(p, vr[lane + 64], a2[t]);
            }
        }
    }

    // output, rounded through bf16 (reference PV einsum outputs bf16)
    #pragma unroll
    for (int t = 0; t < 4; ++t) {
        const int i = wid + 8 * t;
        const size_t ob = ((size_t)(b * NQ + n0 + i)) * DIM + h * HD;
        out[ob + lane]      = __bfloat162float(__float2bfloat16(a0[t]));
        out[ob + lane + 32] = __bfloat162float(__float2bfloat16(a1[t]));
        if (lane < 8)
            out[ob + lane + 64] = __bfloat162float(__float2bfloat16(a2[t]));
    }
}

// ============================================================================
extern "C" void kernel_launch(void* const* d_in, const int* in_sizes, int n_in,
                              void* d_out, int out_size)
{
    (void)in_sizes; (void)n_in; (void)out_size;
    const float* x      = (const float*)d_in[0];
    const float* cond   = (const float*)d_in[1];
    const int*   kvlen  = (const int*)  d_in[2];
    const float* q_w    = (const float*)d_in[3];
    const float* q_b    = (const float*)d_in[4];
    const float* kv_w   = (const float*)d_in[5];
    const float* kv_b   = (const float*)d_in[6];
    const float* proj_w = (const float*)d_in[7];
    const float* proj_b = (const float*)d_in[8];
    const float* qn_w   = (const float*)d_in[9];
    const float* kn_w   = (const float*)d_in[10];
    float* out = (float*)d_out;

    void* p;
    cudaGetSymbolAddress(&p, g_q32);  float* q32 = (float*)p;
    cudaGetSymbolAddress(&p, g_kv32); float* kv32 = (float*)p;
    cudaGetSymbolAddress(&p, g_q16);  __nv_bfloat16* q16 = (__nv_bfloat16*)p;
    cudaGetSymbolAddress(&p, g_k16);  __nv_bfloat16* k16 = (__nv_bfloat16*)p;
    cudaGetSymbolAddress(&p, g_v16);  __nv_bfloat16* v16 = (__nv_bfloat16*)p;
    cudaGetSymbolAddress(&p, g_att);  float* att = (float*)p;

    cudaFuncSetAttribute(attn_scalar, cudaFuncAttributeMaxDynamicSharedMemorySize,
                         SMEM_SCALAR);

    // 1) Q = x @ q_w   (exact fp32, SGEMM accumulation order)
    gemm_f32<<<dim3(DIM / 128, (BB * NQ) / 128), 256>>>(
        x, q_w, nullptr, q32, BB * NQ, DIM, DIM);
    // 2) KV = cond @ kv_w
    gemm_f32<<<dim3((2 * DIM) / 128, (BB * MKV) / 128), 256>>>(
        cond, kv_w, nullptr, kv32, BB * MKV, 2 * DIM, DIM);
    // 3) bias + rmsnorm + bf16
    rms_q_kernel<<<(BB * NQ * NH) / 8, 256>>>(q32, q_b, qn_w, q16);
    rms_kv_kernel<<<(BB * MKV * NH) / 8, 256>>>(kv32, kv_b, kn_w, k16, v16);
    // 4) attention — exact scalar fp32
    attn_scalar<<<dim3(NQ / 32, NH, BB), 256, SMEM_SCALAR>>>(q16, k16, v16, kvlen, att);
    // 5) out = att @ proj_w + proj_b
    gemm_f32<<<dim3(DIM / 128, (BB * NQ) / 128), 256>>>(
        att, proj_w, proj_b, out, BB * NQ, DIM, DIM);
}

// round 8
// speedup vs baseline: 1.3605x; 1.3605x over previous
#include <cuda_runtime.h>
#include <cuda_bf16.h>
#include <mma.h>
#include <cstring>

using namespace nvcuda;

#define BB   4
#define NQ   4096
#define MKV  512
#define DIM  1152
#define NH   16
#define HD   72
#define HDP  80     // head dim padded for 16x16x16 wmma (5 k-steps)

// -------- scratch (static device globals; no allocation) --------
__device__ float          g_q32 [(size_t)BB*NQ*DIM];
__device__ float          g_kv32[(size_t)BB*MKV*2*DIM];
__device__ __nv_bfloat16  g_q16 [(size_t)BB*NQ*NH*HD];
__device__ __nv_bfloat16  g_k16 [(size_t)BB*NH*MKV*HD];
__device__ __nv_bfloat16  g_v16 [(size_t)BB*NH*MKV*HD];
__device__ float          g_att [(size_t)BB*NQ*DIM];

// ============================================================================
// Exact FP32 GEMM, SGEMM-order, with packed f32x2 FMA + double buffering.
// Each C element is ONE ascending-k RN FMA chain — bit-identical to the R7
// scalar version (f32x2 lanes are independent RN ops).
// 256 threads, block tile 128x128, kc=16, per-thread 8x8 micro-tile.
// ============================================================================
#define KC  16
#define SLD 132

__device__ __forceinline__ void fma2(unsigned long long& d,
                                     unsigned long long a,
                                     unsigned long long b)
{
    asm("fma.rn.f32x2 %0, %1, %2, %3;" : "=l"(d) : "l"(a), "l"(b), "l"(d));
}
__device__ __forceinline__ unsigned long long pack2(float x)
{
    unsigned long long r;
    asm("mov.b64 %0, {%1, %1};" : "=l"(r) : "f"(x));
    return r;
}

__global__ void __launch_bounds__(256) gemm_f32(
    const float* __restrict__ A, const float* __restrict__ B,
    const float* __restrict__ bias, float* __restrict__ C,
    int M, int N, int K)
{
    __shared__ float As[2][KC][SLD];   // transposed: As[k][m]
    __shared__ float Bs[2][KC][SLD];   // Bs[k][n]

    const int tid = threadIdx.x;
    const int tx  = tid & 15;
    const int ty  = tid >> 4;
    const int m0  = blockIdx.y * 128;
    const int n0  = blockIdx.x * 128;

    const int ar = tid >> 2, ac = (tid & 3) * 4;   // A stage coords
    const int br = tid >> 5, bc = (tid & 31) * 4;  // B stage coords

    unsigned long long acc2[8][4];
    #pragma unroll
    for (int i = 0; i < 8; ++i)
        #pragma unroll
        for (int j = 0; j < 4; ++j) acc2[i][j] = 0ull;

    const int T = K / KC;
    float4 pa0, pa1, pb0, pb1;

    // prefetch tile 0 and stage
    pa0 = *(const float4*)&A[(size_t)(m0 + ar) * K + ac];
    pa1 = *(const float4*)&A[(size_t)(m0 + ar + 64) * K + ac];
    pb0 = *(const float4*)&B[(size_t)br * N + n0 + bc];
    pb1 = *(const float4*)&B[(size_t)(br + 8) * N + n0 + bc];
    {
        As[0][ac + 0][ar] = pa0.x; As[0][ac + 1][ar] = pa0.y;
        As[0][ac + 2][ar] = pa0.z; As[0][ac + 3][ar] = pa0.w;
        As[0][ac + 0][ar + 64] = pa1.x; As[0][ac + 1][ar + 64] = pa1.y;
        As[0][ac + 2][ar + 64] = pa1.z; As[0][ac + 3][ar + 64] = pa1.w;
        *(float4*)&Bs[0][br][bc] = pb0;
        *(float4*)&Bs[0][br + 8][bc] = pb1;
    }
    __syncthreads();

    for (int t = 0; t < T; ++t) {
        const int buf = t & 1;
        if (t + 1 < T) {
            const int kt = (t + 1) * KC;
            pa0 = *(const float4*)&A[(size_t)(m0 + ar) * K + kt + ac];
            pa1 = *(const float4*)&A[(size_t)(m0 + ar + 64) * K + kt + ac];
            pb0 = *(const float4*)&B[(size_t)(kt + br) * N + n0 + bc];
            pb1 = *(const float4*)&B[(size_t)(kt + br + 8) * N + n0 + bc];
        }

        #pragma unroll
        for (int kk = 0; kk < KC; ++kk) {
            float4 av0 = *(const float4*)&As[buf][kk][ty * 8];
            float4 av1 = *(const float4*)&As[buf][kk][ty * 8 + 4];
            float4 bv0 = *(const float4*)&Bs[buf][kk][tx * 8];
            float4 bv1 = *(const float4*)&Bs[buf][kk][tx * 8 + 4];
            unsigned long long b2[4];
            memcpy(&b2[0], &bv0, 16);
            memcpy(&b2[2], &bv1, 16);
            float a[8] = {av0.x, av0.y, av0.z, av0.w, av1.x, av1.y, av1.z, av1.w};
            #pragma unroll
            for (int i = 0; i < 8; ++i) {
                unsigned long long a2 = pack2(a[i]);
                #pragma unroll
                for (int jp = 0; jp < 4; ++jp)
                    fma2(acc2[i][jp], a2, b2[jp]);
            }
        }
        __syncthreads();

        if (t + 1 < T) {
            const int nb = buf ^ 1;
            As[nb][ac + 0][ar] = pa0.x; As[nb][ac + 1][ar] = pa0.y;
            As[nb][ac + 2][ar] = pa0.z; As[nb][ac + 3][ar] = pa0.w;
            As[nb][ac + 0][ar + 64] = pa1.x; As[nb][ac + 1][ar + 64] = pa1.y;
            As[nb][ac + 2][ar + 64] = pa1.z; As[nb][ac + 3][ar + 64] = pa1.w;
            *(float4*)&Bs[nb][br][bc] = pb0;
            *(float4*)&Bs[nb][br + 8][bc] = pb1;
            __syncthreads();
        }
    }

    // epilogue: optional bias, float4 stores
    #pragma unroll
    for (int i = 0; i < 8; ++i) {
        const size_t gm = m0 + ty * 8 + i;
        const int    gn = n0 + tx * 8;
        float o[8];
        memcpy(o, acc2[i], 32);
        if (bias) {
            #pragma unroll
            for (int j = 0; j < 8; ++j) o[j] += bias[gn + j];
        }
        *(float4*)&C[gm * N + gn]     = *(float4*)(o);
        *(float4*)&C[gm * N + gn + 4] = *(float4*)(o + 4);
    }
}

// ============================================================================
// Q path: bias + RMSNorm + bf16 cast. One warp per (b,n,h).
// ============================================================================
__global__ void __launch_bounds__(256) rms_q_kernel(
    const float* __restrict__ q32, const float* __restrict__ qb,
    const float* __restrict__ qw, __nv_bfloat16* __restrict__ q16)
{
    const int wid  = threadIdx.x >> 5;
    const int lane = threadIdx.x & 31;
    const size_t row = (size_t)blockIdx.x * 8 + wid;
    const int h = (int)(row % NH);
    const float* src = q32 + row * HD;

    float v0 = src[lane]      + qb[h * HD + lane];
    float v1 = src[lane + 32] + qb[h * HD + lane + 32];
    float v2 = (lane < 8) ? src[lane + 64] + qb[h * HD + lane + 64] : 0.0f;

    float ss = v0 * v0 + v1 * v1 + v2 * v2;
    #pragma unroll
    for (int o = 16; o; o >>= 1) ss += __shfl_xor_sync(0xffffffffu, ss, o);
    const float inv = 1.0f / sqrtf(ss * (1.0f / 72.0f) + 1e-6f);

    __nv_bfloat16* dst = q16 + row * HD;
    dst[lane]      = __float2bfloat16(v0 * inv * qw[lane]);
    dst[lane + 32] = __float2bfloat16(v1 * inv * qw[lane + 32]);
    if (lane < 8)
        dst[lane + 64] = __float2bfloat16(v2 * inv * qw[lane + 64]);
}

// ============================================================================
// KV path: bias + RMSNorm(k) + cast(v), transpose to [b][h][m][d].
// ============================================================================
__global__ void __launch_bounds__(256) rms_kv_kernel(
    const float* __restrict__ kv32, const float* __restrict__ kvb,
    const float* __restrict__ knw,
    __nv_bfloat16* __restrict__ k16, __nv_bfloat16* __restrict__ v16)
{
    const int wid  = threadIdx.x >> 5;
    const int lane = threadIdx.x & 31;
    const int rid  = blockIdx.x * 8 + wid;
    const int b = rid / (MKV * NH);
    const int m = (rid / NH) % MKV;
    const int h = rid % NH;

    const size_t base = ((size_t)(b * MKV + m) * 2) * DIM + h * HD;
    const float* ksrc = kv32 + base;
    const float* vsrc = kv32 + base + DIM;
    const float* kb   = kvb + h * HD;
    const float* vb   = kvb + DIM + h * HD;
    const size_t obase = ((size_t)(b * NH + h) * MKV + m) * HD;

    float k0 = ksrc[lane]      + kb[lane];
    float k1 = ksrc[lane + 32] + kb[lane + 32];
    float k2 = (lane < 8) ? ksrc[lane + 64] + kb[lane + 64] : 0.0f;
    float ss = k0 * k0 + k1 * k1 + k2 * k2;
    #pragma unroll
    for (int o = 16; o; o >>= 1) ss += __shfl_xor_sync(0xffffffffu, ss, o);
    const float inv = 1.0f / sqrtf(ss * (1.0f / 72.0f) + 1e-6f);
    k16[obase + lane]      = __float2bfloat16(k0 * inv * knw[lane]);
    k16[obase + lane + 32] = __float2bfloat16(k1 * inv * knw[lane + 32]);
    if (lane < 8)
        k16[obase + lane + 64] = __float2bfloat16(k2 * inv * knw[lane + 64]);

    v16[obase + lane]      = __float2bfloat16(vsrc[lane]      + vb[lane]);
    v16[obase + lane + 32] = __float2bfloat16(vsrc[lane + 32] + vb[lane + 32]);
    if (lane < 8)
        v16[obase + lane + 64] = __float2bfloat16(vsrc[lane + 64] + vb[lane + 64]);
}

// ============================================================================
// WMMA bf16 attention (validated numerically equal to scalar in R3/R4).
// One block per (b, h, 32-query tile), 8 warps. kvlen chunk-skipping.
// ============================================================================
#define SMEM_ATTN ((32*HDP + 128*HDP)*2 + 32*MKV*4 + 32*MKV*2)

__global__ void __launch_bounds__(256) attn_wmma(
    const __nv_bfloat16* __restrict__ q16, const __nv_bfloat16* __restrict__ k16,
    const __nv_bfloat16* __restrict__ v16, const int* __restrict__ kvlen_p,
    float* __restrict__ out)
{
    extern __shared__ char smem[];
    __nv_bfloat16* qs = (__nv_bfloat16*)smem;                        // [32][80]
    __nv_bfloat16* ks = qs + 32 * HDP;                               // [128][80]
    float*         sc = (float*)(smem + (32 * HDP + 128 * HDP) * 2); // [32][512]
    __nv_bfloat16* pb = (__nv_bfloat16*)(smem + (32 * HDP + 128 * HDP) * 2 + 32 * MKV * 4);

    const int tid  = threadIdx.x;
    const int wid  = tid >> 5;
    const int lane = tid & 31;
    const int n0 = blockIdx.x * 32;
    const int h  = blockIdx.y;
    const int b  = blockIdx.z;
    const int kvlen = kvlen_p[b];
    const int nchunks = (kvlen + 127) >> 7;
    const float scale = 0.11785113019775793f;   // 1/sqrt(72)

    // load Q tile (pad cols 72..79 with 0)
    const size_t qbase = (((size_t)(b * NQ + n0)) * NH + h) * HD;
    for (int i = tid; i < 32 * HDP; i += 256) {
        int r = i / HDP, c = i % HDP;
        qs[i] = (c < HD) ? q16[qbase + (size_t)r * NH * HD + c] : __float2bfloat16(0.0f);
    }

    const size_t kvbase = ((size_t)(b * NH + h)) * MKV * HD;

    // ---------------- Phase 1: scores ----------------
    for (int mc = 0; mc < nchunks; ++mc) {
        __syncthreads();
        for (int i = tid; i < 128 * HDP; i += 256) {
            int r = i / HDP, c = i % HDP;
            ks[i] = (c < HD) ? k16[kvbase + (size_t)(mc * 128 + r) * HD + c]
                             : __float2bfloat16(0.0f);
        }
        __syncthreads();
        const int rt = wid >> 2;
        const int cp = wid & 3;
        wmma::fragment<wmma::matrix_a, 16, 16, 16, __nv_bfloat16, wmma::row_major> af;
        wmma::fragment<wmma::matrix_b, 16, 16, 16, __nv_bfloat16, wmma::col_major> bf;
        #pragma unroll
        for (int cc = 0; cc < 2; ++cc) {
            const int ct = cp * 2 + cc;
            wmma::fragment<wmma::accumulator, 16, 16, 16, float> acc;
            wmma::fill_fragment(acc, 0.0f);
            #pragma unroll
            for (int kk = 0; kk < 5; ++kk) {
                wmma::load_matrix_sync(af, qs + rt * 16 * HDP + kk * 16, HDP);
                wmma::load_matrix_sync(bf, ks + ct * 16 * HDP + kk * 16, HDP);
                wmma::mma_sync(acc, af, bf, acc);
            }
            wmma::store_matrix_sync(sc + rt * 16 * MKV + mc * 128 + ct * 16, acc,
                                    MKV, wmma::mem_row_major);
        }
    }
    __syncthreads();

    // ---------------- Phase 2: masked softmax (division, matching R7) --------
    const int jlim = nchunks * 128;
    for (int i = wid; i < 32; i += 8) {
        float* row = sc + (size_t)i * MKV;
        float mx = -1e30f;
        for (int j = lane; j < kvlen; j += 32) {
            float s = row[j] * scale;
            row[j] = s;
            mx = fmaxf(mx, s);
        }
        #pragma unroll
        for (int o = 16; o; o >>= 1) mx = fmaxf(mx, __shfl_xor_sync(0xffffffffu, mx, o));
        float sum = 0.0f;
        for (int j = lane; j < kvlen; j += 32) {
            float e = expf(row[j] - mx);
            row[j] = e; sum += e;
        }
        #pragma unroll
        for (int o = 16; o; o >>= 1) sum += __shfl_xor_sync(0xffffffffu, sum, o);
        for (int j = lane; j < kvlen; j += 32)
            pb[(size_t)i * MKV + j] = __float2bfloat16(row[j] / sum);
        for (int j = kvlen + lane; j < jlim; j += 32)        // zero pad to chunk end
            pb[(size_t)i * MKV + j] = __float2bfloat16(0.0f);
    }
    __syncthreads();

    // ---------------- Phase 3: O = P V ----------------
    wmma::fragment<wmma::accumulator, 16, 16, 16, float> pv[2];
    int fr[2], fc[2], nf = 0;
    for (int t = wid; t < 10; t += 8) {        // 2x5 out tiles over 8 warps
        fr[nf] = t / 5; fc[nf] = t % 5;
        wmma::fill_fragment(pv[nf], 0.0f);
        ++nf;
    }
    for (int mc = 0; mc < nchunks; ++mc) {
        __syncthreads();
        for (int i = tid; i < 128 * HDP; i += 256) {
            int r = i / HDP, c = i % HDP;
            ks[i] = (c < HD) ? v16[kvbase + (size_t)(mc * 128 + r) * HD + c]
                             : __float2bfloat16(0.0f);
        }
        __syncthreads();
        wmma::fragment<wmma::matrix_a, 16, 16, 16, __nv_bfloat16, wmma::row_major> pf;
        wmma::fragment<wmma::matrix_b, 16, 16, 16, __nv_bfloat16, wmma::row_major> vf;
        for (int q = 0; q < nf; ++q) {
            #pragma unroll
            for (int kk = 0; kk < 8; ++kk) {
                wmma::load_matrix_sync(pf, pb + (size_t)fr[q] * 16 * MKV + mc * 128 + kk * 16, MKV);
                wmma::load_matrix_sync(vf, ks + kk * 16 * HDP + fc[q] * 16, HDP);
                wmma::mma_sync(pv[q], pf, vf, pv[q]);
            }
        }
    }
    __syncthreads();
    // stage out through smem (reuse score buffer), round through bf16
    float* os = sc;   // [32][80]
    for (int q = 0; q < nf; ++q)
        wmma::store_matrix_sync(os + fr[q] * 16 * HDP + fc[q] * 16, pv[q], HDP,
                                wmma::mem_row_major);
    __syncthreads();
    for (int i = tid; i < 32 * HD; i += 256) {
        int r = i / HD, d = i % HD;
        out[((size_t)(b * NQ + n0 + r)) * DIM + h * HD + d] =
            __bfloat162float(__float2bfloat16(os[r * HDP + d]));
    }
}

// ============================================================================
extern "C" void kernel_launch(void* const* d_in, const int* in_sizes, int n_in,
                              void* d_out, int out_size)
{
    (void)in_sizes; (void)n_in; (void)out_size;
    const float* x      = (const float*)d_in[0];
    const float* cond   = (const float*)d_in[1];
    const int*   kvlen  = (const int*)  d_in[2];
    const float* q_w    = (const float*)d_in[3];
    const float* q_b    = (const float*)d_in[4];
    const float* kv_w   = (const float*)d_in[5];
    const float* kv_b   = (const float*)d_in[6];
    const float* proj_w = (const float*)d_in[7];
    const float* proj_b = (const float*)d_in[8];
    const float* qn_w   = (const float*)d_in[9];
    const float* kn_w   = (const float*)d_in[10];
    float* out = (float*)d_out;

    void* p;
    cudaGetSymbolAddress(&p, g_q32);  float* q32 = (float*)p;
    cudaGetSymbolAddress(&p, g_kv32); float* kv32 = (float*)p;
    cudaGetSymbolAddress(&p, g_q16);  __nv_bfloat16* q16 = (__nv_bfloat16*)p;
    cudaGetSymbolAddress(&p, g_k16);  __nv_bfloat16* k16 = (__nv_bfloat16*)p;
    cudaGetSymbolAddress(&p, g_v16);  __nv_bfloat16* v16 = (__nv_bfloat16*)p;
    cudaGetSymbolAddress(&p, g_att);  float* att = (float*)p;

    cudaFuncSetAttribute(attn_wmma, cudaFuncAttributeMaxDynamicSharedMemorySize,
                         SMEM_ATTN);

    // 1) Q = x @ q_w   (exact fp32, SGEMM accumulation order, f32x2 packed)
    gemm_f32<<<dim3(DIM / 128, (BB * NQ) / 128), 256>>>(
        x, q_w, nullptr, q32, BB * NQ, DIM, DIM);
    // 2) KV = cond @ kv_w
    gemm_f32<<<dim3((2 * DIM) / 128, (BB * MKV) / 128), 256>>>(
        cond, kv_w, nullptr, kv32, BB * MKV, 2 * DIM, DIM);
    // 3) bias + rmsnorm + bf16
    rms_q_kernel<<<(BB * NQ * NH) / 8, 256>>>(q32, q_b, qn_w, q16);
    rms_kv_kernel<<<(BB * MKV * NH) / 8, 256>>>(kv32, kv_b, kn_w, k16, v16);
    // 4) attention — wmma bf16, kvlen chunk-skipping
    attn_wmma<<<dim3(NQ / 32, NH, BB), 256, SMEM_ATTN>>>(q16, k16, v16, kvlen, att);
    // 5) out = att @ proj_w + proj_b
    gemm_f32<<<dim3(DIM / 128, (BB * NQ) / 128), 256>>>(
        att, proj_w, proj_b, out, BB * NQ, DIM, DIM);
}

// round 9
// speedup vs baseline: 1.4990x; 1.1017x over previous
#include <cuda_runtime.h>
#include <cuda_bf16.h>
#include <mma.h>
#include <cstring>

using namespace nvcuda;

#define BB   4
#define NQ   4096
#define MKV  512
#define DIM  1152
#define NH   16
#define HD   72
#define HDP  80     // head dim padded for 16x16x16 wmma (5 k-steps)

// -------- scratch (static device globals; no allocation) --------
__device__ float          g_q32  [(size_t)BB*NQ*DIM];
__device__ float          g_kv32 [(size_t)BB*MKV*2*DIM];
__device__ __nv_bfloat16  g_q16  [(size_t)BB*NQ*NH*HD];
__device__ __nv_bfloat16  g_k16  [(size_t)BB*NH*MKV*HD];
__device__ __nv_bfloat16  g_v16  [(size_t)BB*NH*MKV*HD];
__device__ __nv_bfloat16  g_att16[(size_t)BB*NQ*DIM];    // attention out, exact bf16

// ============================================================================
// Exact FP32 GEMM (Q/KV projections — upstream of bf16 snaps, must be exact).
// SGEMM-order ascending-k chains, packed f32x2 FMA, double-buffered smem.
// ============================================================================
#define KC  16
#define SLD 132

__device__ __forceinline__ void fma2(unsigned long long& d,
                                     unsigned long long a,
                                     unsigned long long b)
{
    asm("fma.rn.f32x2 %0, %1, %2, %3;" : "=l"(d) : "l"(a), "l"(b), "l"(d));
}
__device__ __forceinline__ unsigned long long pack2(float x)
{
    unsigned long long r;
    asm("mov.b64 %0, {%1, %1};" : "=l"(r) : "f"(x));
    return r;
}

__global__ void __launch_bounds__(256) gemm_f32(
    const float* __restrict__ A, const float* __restrict__ B,
    const float* __restrict__ bias, float* __restrict__ C,
    int M, int N, int K)
{
    __shared__ float As[2][KC][SLD];
    __shared__ float Bs[2][KC][SLD];

    const int tid = threadIdx.x;
    const int tx  = tid & 15;
    const int ty  = tid >> 4;
    const int m0  = blockIdx.y * 128;
    const int n0  = blockIdx.x * 128;

    const int ar = tid >> 2, ac = (tid & 3) * 4;
    const int br = tid >> 5, bc = (tid & 31) * 4;

    unsigned long long acc2[8][4];
    #pragma unroll
    for (int i = 0; i < 8; ++i)
        #pragma unroll
        for (int j = 0; j < 4; ++j) acc2[i][j] = 0ull;

    const int T = K / KC;
    float4 pa0, pa1, pb0, pb1;

    pa0 = *(const float4*)&A[(size_t)(m0 + ar) * K + ac];
    pa1 = *(const float4*)&A[(size_t)(m0 + ar + 64) * K + ac];
    pb0 = *(const float4*)&B[(size_t)br * N + n0 + bc];
    pb1 = *(const float4*)&B[(size_t)(br + 8) * N + n0 + bc];
    {
        As[0][ac + 0][ar] = pa0.x; As[0][ac + 1][ar] = pa0.y;
        As[0][ac + 2][ar] = pa0.z; As[0][ac + 3][ar] = pa0.w;
        As[0][ac + 0][ar + 64] = pa1.x; As[0][ac + 1][ar + 64] = pa1.y;
        As[0][ac + 2][ar + 64] = pa1.z; As[0][ac + 3][ar + 64] = pa1.w;
        *(float4*)&Bs[0][br][bc] = pb0;
        *(float4*)&Bs[0][br + 8][bc] = pb1;
    }
    __syncthreads();

    for (int t = 0; t < T; ++t) {
        const int buf = t & 1;
        if (t + 1 < T) {
            const int kt = (t + 1) * KC;
            pa0 = *(const float4*)&A[(size_t)(m0 + ar) * K + kt + ac];
            pa1 = *(const float4*)&A[(size_t)(m0 + ar + 64) * K + kt + ac];
            pb0 = *(const float4*)&B[(size_t)(kt + br) * N + n0 + bc];
            pb1 = *(const float4*)&B[(size_t)(kt + br + 8) * N + n0 + bc];
        }

        #pragma unroll
        for (int kk = 0; kk < KC; ++kk) {
            float4 av0 = *(const float4*)&As[buf][kk][ty * 8];
            float4 av1 = *(const float4*)&As[buf][kk][ty * 8 + 4];
            float4 bv0 = *(const float4*)&Bs[buf][kk][tx * 8];
            float4 bv1 = *(const float4*)&Bs[buf][kk][tx * 8 + 4];
            unsigned long long b2[4];
            memcpy(&b2[0], &bv0, 16);
            memcpy(&b2[2], &bv1, 16);
            float a[8] = {av0.x, av0.y, av0.z, av0.w, av1.x, av1.y, av1.z, av1.w};
            #pragma unroll
            for (int i = 0; i < 8; ++i) {
                unsigned long long a2 = pack2(a[i]);
                #pragma unroll
                for (int jp = 0; jp < 4; ++jp)
                    fma2(acc2[i][jp], a2, b2[jp]);
            }
        }
        __syncthreads();

        if (t + 1 < T) {
            const int nb = buf ^ 1;
            As[nb][ac + 0][ar] = pa0.x; As[nb][ac + 1][ar] = pa0.y;
            As[nb][ac + 2][ar] = pa0.z; As[nb][ac + 3][ar] = pa0.w;
            As[nb][ac + 0][ar + 64] = pa1.x; As[nb][ac + 1][ar + 64] = pa1.y;
            As[nb][ac + 2][ar + 64] = pa1.z; As[nb][ac + 3][ar + 64] = pa1.w;
            *(float4*)&Bs[nb][br][bc] = pb0;
            *(float4*)&Bs[nb][br + 8][bc] = pb1;
            __syncthreads();
        }
    }

    #pragma unroll
    for (int i = 0; i < 8; ++i) {
        const size_t gm = m0 + ty * 8 + i;
        const int    gn = n0 + tx * 8;
        float o[8];
        memcpy(o, acc2[i], 32);
        if (bias) {
            #pragma unroll
            for (int j = 0; j < 8; ++j) o[j] += bias[gn + j];
        }
        *(float4*)&C[gm * N + gn]     = *(float4*)(o);
        *(float4*)&C[gm * N + gn + 4] = *(float4*)(o + 4);
    }
}

// ============================================================================
// Output projection: bf16x2 tensor-core GEMM.
// A (attention out) is EXACTLY bf16-valued -> no A split needed.
// B = proj_w split hi/lo (RNE); C = A*Bh + A*Bl + bias, fp32 accum.
// Dropped residual ~2^-16 contributes ~5e-6 directly (no snap downstream).
// 256 thr, block tile 128x128x32, 8 warps 4x2, warp tile 32x64.
// ============================================================================
#define OALD 40
#define OBLD 136

__global__ void __launch_bounds__(256) gemm_out_bf16(
    const __nv_bfloat16* __restrict__ A, const float* __restrict__ B,
    const float* __restrict__ bias, float* __restrict__ C,
    int M, int N, int K)
{
    __shared__ __nv_bfloat16 Asm[128 * OALD];
    __shared__ __nv_bfloat16 Bh [32 * OBLD];
    __shared__ __nv_bfloat16 Bl [32 * OBLD];

    const int tid = threadIdx.x;
    const int wid = tid >> 5;
    const int m0  = blockIdx.y * 128;
    const int n0  = blockIdx.x * 128;
    const int wr  = wid >> 1;          // 0..3 : 32-row strip
    const int wc  = wid & 1;           // 0..1 : 64-col strip

    wmma::fragment<wmma::accumulator, 16, 16, 16, float> acc[2][4];
    #pragma unroll
    for (int r = 0; r < 2; ++r)
        #pragma unroll
        for (int c = 0; c < 4; ++c)
            wmma::fill_fragment(acc[r][c], 0.0f);

    const int arow = tid >> 1, acol = (tid & 1) * 16;   // A stage: 128x32 bf16
    const int brow = tid >> 3, bcol = (tid & 7) * 16;   // B stage: 32x128 f32

    for (int kt = 0; kt < K; kt += 32) {
        // stage A (two uint4 = 16 bf16)
        {
            const __nv_bfloat16* src = &A[(size_t)(m0 + arow) * K + kt + acol];
            *(uint4*)&Asm[arow * OALD + acol]     = *(const uint4*)src;
            *(uint4*)&Asm[arow * OALD + acol + 8] = *(const uint4*)(src + 8);
        }
        // stage B with hi/lo split
        {
            const float* src = &B[(size_t)(kt + brow) * N + n0 + bcol];
            #pragma unroll
            for (int q = 0; q < 4; ++q) {
                float4 v = *(const float4*)(src + q * 4);
                #pragma unroll
                for (int e = 0; e < 4; ++e) {
                    float f = (&v.x)[e];
                    __nv_bfloat16 h = __float2bfloat16(f);
                    Bh[brow * OBLD + bcol + q * 4 + e] = h;
                    Bl[brow * OBLD + bcol + q * 4 + e] =
                        __float2bfloat16(f - __bfloat162float(h));
                }
            }
        }
        __syncthreads();

        #pragma unroll
        for (int kk = 0; kk < 32; kk += 16) {
            wmma::fragment<wmma::matrix_a, 16, 16, 16, __nv_bfloat16, wmma::row_major> af[2];
            wmma::fragment<wmma::matrix_b, 16, 16, 16, __nv_bfloat16, wmma::row_major> bhf[4], blf[4];
            #pragma unroll
            for (int r = 0; r < 2; ++r)
                wmma::load_matrix_sync(af[r], Asm + (wr * 32 + r * 16) * OALD + kk, OALD);
            #pragma unroll
            for (int c = 0; c < 4; ++c) {
                wmma::load_matrix_sync(bhf[c], Bh + kk * OBLD + wc * 64 + c * 16, OBLD);
                wmma::load_matrix_sync(blf[c], Bl + kk * OBLD + wc * 64 + c * 16, OBLD);
            }
            #pragma unroll
            for (int r = 0; r < 2; ++r)
                #pragma unroll
                for (int c = 0; c < 4; ++c) {
                    wmma::mma_sync(acc[r][c], af[r], blf[c], acc[r][c]);
                    wmma::mma_sync(acc[r][c], af[r], bhf[c], acc[r][c]);
                }
        }
        __syncthreads();
    }

    // epilogue: bias add via per-warp smem scratch, coalesced stores
    #pragma unroll
    for (int r = 0; r < 2; ++r)
        #pragma unroll
        for (int c = 0; c < 4; ++c) {
            const int gm = m0 + wr * 32 + r * 16;
            const int gn = n0 + wc * 64 + c * 16;
            float* tb = (float*)Asm + wid * 16 * 20;
            wmma::store_matrix_sync(tb, acc[r][c], 20, wmma::mem_row_major);
            __syncwarp();
            const int lane = tid & 31;
            #pragma unroll
            for (int e = lane; e < 256; e += 32) {
                int rr = e >> 4, cc = e & 15;
                C[(size_t)(gm + rr) * N + gn + cc] = tb[rr * 20 + cc] + bias[gn + cc];
            }
            __syncwarp();
        }
}

// ============================================================================
// Q path: bias + RMSNorm + bf16 cast. One warp per (b,n,h).
// ============================================================================
__global__ void __launch_bounds__(256) rms_q_kernel(
    const float* __restrict__ q32, const float* __restrict__ qb,
    const float* __restrict__ qw, __nv_bfloat16* __restrict__ q16)
{
    const int wid  = threadIdx.x >> 5;
    const int lane = threadIdx.x & 31;
    const size_t row = (size_t)blockIdx.x * 8 + wid;
    const int h = (int)(row % NH);
    const float* src = q32 + row * HD;

    float v0 = src[lane]      + qb[h * HD + lane];
    float v1 = src[lane + 32] + qb[h * HD + lane + 32];
    float v2 = (lane < 8) ? src[lane + 64] + qb[h * HD + lane + 64] : 0.0f;

    float ss = v0 * v0 + v1 * v1 + v2 * v2;
    #pragma unroll
    for (int o = 16; o; o >>= 1) ss += __shfl_xor_sync(0xffffffffu, ss, o);
    const float inv = 1.0f / sqrtf(ss * (1.0f / 72.0f) + 1e-6f);

    __nv_bfloat16* dst = q16 + row * HD;
    dst[lane]      = __float2bfloat16(v0 * inv * qw[lane]);
    dst[lane + 32] = __float2bfloat16(v1 * inv * qw[lane + 32]);
    if (lane < 8)
        dst[lane + 64] = __float2bfloat16(v2 * inv * qw[lane + 64]);
}

// ============================================================================
// KV path: bias + RMSNorm(k) + cast(v), transpose to [b][h][m][d].
// ============================================================================
__global__ void __launch_bounds__(256) rms_kv_kernel(
    const float* __restrict__ kv32, const float* __restrict__ kvb,
    const float* __restrict__ knw,
    __nv_bfloat16* __restrict__ k16, __nv_bfloat16* __restrict__ v16)
{
    const int wid  = threadIdx.x >> 5;
    const int lane = threadIdx.x & 31;
    const int rid  = blockIdx.x * 8 + wid;
    const int b = rid / (MKV * NH);
    const int m = (rid / NH) % MKV;
    const int h = rid % NH;

    const size_t base = ((size_t)(b * MKV + m) * 2) * DIM + h * HD;
    const float* ksrc = kv32 + base;
    const float* vsrc = kv32 + base + DIM;
    const float* kb   = kvb + h * HD;
    const float* vb   = kvb + DIM + h * HD;
    const size_t obase = ((size_t)(b * NH + h) * MKV + m) * HD;

    float k0 = ksrc[lane]      + kb[lane];
    float k1 = ksrc[lane + 32] + kb[lane + 32];
    float k2 = (lane < 8) ? ksrc[lane + 64] + kb[lane + 64] : 0.0f;
    float ss = k0 * k0 + k1 * k1 + k2 * k2;
    #pragma unroll
    for (int o = 16; o; o >>= 1) ss += __shfl_xor_sync(0xffffffffu, ss, o);
    const float inv = 1.0f / sqrtf(ss * (1.0f / 72.0f) + 1e-6f);
    k16[obase + lane]      = __float2bfloat16(k0 * inv * knw[lane]);
    k16[obase + lane + 32] = __float2bfloat16(k1 * inv * knw[lane + 32]);
    if (lane < 8)
        k16[obase + lane + 64] = __float2bfloat16(k2 * inv * knw[lane + 64]);

    v16[obase + lane]      = __float2bfloat16(vsrc[lane]      + vb[lane]);
    v16[obase + lane + 32] = __float2bfloat16(vsrc[lane + 32] + vb[lane + 32]);
    if (lane < 8)
        v16[obase + lane + 64] = __float2bfloat16(vsrc[lane + 64] + vb[lane + 64]);
}

// ============================================================================
// WMMA bf16 attention. Output written directly as bf16 (exact).
// ============================================================================
#define SMEM_ATTN ((32*HDP + 128*HDP)*2 + 32*MKV*4 + 32*MKV*2)

__global__ void __launch_bounds__(256) attn_wmma(
    const __nv_bfloat16* __restrict__ q16, const __nv_bfloat16* __restrict__ k16,
    const __nv_bfloat16* __restrict__ v16, const int* __restrict__ kvlen_p,
    __nv_bfloat16* __restrict__ out)
{
    extern __shared__ char smem[];
    __nv_bfloat16* qs = (__nv_bfloat16*)smem;                        // [32][80]
    __nv_bfloat16* ks = qs + 32 * HDP;                               // [128][80]
    float*         sc = (float*)(smem + (32 * HDP + 128 * HDP) * 2); // [32][512]
    __nv_bfloat16* pb = (__nv_bfloat16*)(smem + (32 * HDP + 128 * HDP) * 2 + 32 * MKV * 4);

    const int tid  = threadIdx.x;
    const int wid  = tid >> 5;
    const int lane = tid & 31;
    const int n0 = blockIdx.x * 32;
    const int h  = blockIdx.y;
    const int b  = blockIdx.z;
    const int kvlen = kvlen_p[b];
    const int nchunks = (kvlen + 127) >> 7;
    const float scale = 0.11785113019775793f;   // 1/sqrt(72)

    const size_t qbase = (((size_t)(b * NQ + n0)) * NH + h) * HD;
    for (int i = tid; i < 32 * HDP; i += 256) {
        int r = i / HDP, c = i % HDP;
        qs[i] = (c < HD) ? q16[qbase + (size_t)r * NH * HD + c] : __float2bfloat16(0.0f);
    }

    const size_t kvbase = ((size_t)(b * NH + h)) * MKV * HD;

    // ---------------- Phase 1: scores ----------------
    for (int mc = 0; mc < nchunks; ++mc) {
        __syncthreads();
        for (int i = tid; i < 128 * HDP; i += 256) {
            int r = i / HDP, c = i % HDP;
            ks[i] = (c < HD) ? k16[kvbase + (size_t)(mc * 128 + r) * HD + c]
                             : __float2bfloat16(0.0f);
        }
        __syncthreads();
        const int rt = wid >> 2;
        const int cp = wid & 3;
        wmma::fragment<wmma::matrix_a, 16, 16, 16, __nv_bfloat16, wmma::row_major> af;
        wmma::fragment<wmma::matrix_b, 16, 16, 16, __nv_bfloat16, wmma::col_major> bf;
        #pragma unroll
        for (int cc = 0; cc < 2; ++cc) {
            const int ct = cp * 2 + cc;
            wmma::fragment<wmma::accumulator, 16, 16, 16, float> acc;
            wmma::fill_fragment(acc, 0.0f);
            #pragma unroll
            for (int kk = 0; kk < 5; ++kk) {
                wmma::load_matrix_sync(af, qs + rt * 16 * HDP + kk * 16, HDP);
                wmma::load_matrix_sync(bf, ks + ct * 16 * HDP + kk * 16, HDP);
                wmma::mma_sync(acc, af, bf, acc);
            }
            wmma::store_matrix_sync(sc + rt * 16 * MKV + mc * 128 + ct * 16, acc,
                                    MKV, wmma::mem_row_major);
        }
    }
    __syncthreads();

    // ---------------- Phase 2: masked softmax ----------------
    const int jlim = nchunks * 128;
    for (int i = wid; i < 32; i += 8) {
        float* row = sc + (size_t)i * MKV;
        float mx = -1e30f;
        for (int j = lane; j < kvlen; j += 32) {
            float s = row[j] * scale;
            row[j] = s;
            mx = fmaxf(mx, s);
        }
        #pragma unroll
        for (int o = 16; o; o >>= 1) mx = fmaxf(mx, __shfl_xor_sync(0xffffffffu, mx, o));
        float sum = 0.0f;
        for (int j = lane; j < kvlen; j += 32) {
            float e = expf(row[j] - mx);
            row[j] = e; sum += e;
        }
        #pragma unroll
        for (int o = 16; o; o >>= 1) sum += __shfl_xor_sync(0xffffffffu, sum, o);
        for (int j = lane; j < kvlen; j += 32)
            pb[(size_t)i * MKV + j] = __float2bfloat16(row[j] / sum);
        for (int j = kvlen + lane; j < jlim; j += 32)
            pb[(size_t)i * MKV + j] = __float2bfloat16(0.0f);
    }
    __syncthreads();

    // ---------------- Phase 3: O = P V ----------------
    wmma::fragment<wmma::accumulator, 16, 16, 16, float> pv[2];
    int fr[2], fc[2], nf = 0;
    for (int t = wid; t < 10; t += 8) {
        fr[nf] = t / 5; fc[nf] = t % 5;
        wmma::fill_fragment(pv[nf], 0.0f);
        ++nf;
    }
    for (int mc = 0; mc < nchunks; ++mc) {
        __syncthreads();
        for (int i = tid; i < 128 * HDP; i += 256) {
            int r = i / HDP, c = i % HDP;
            ks[i] = (c < HD) ? v16[kvbase + (size_t)(mc * 128 + r) * HD + c]
                             : __float2bfloat16(0.0f);
        }
        __syncthreads();
        wmma::fragment<wmma::matrix_a, 16, 16, 16, __nv_bfloat16, wmma::row_major> pf;
        wmma::fragment<wmma::matrix_b, 16, 16, 16, __nv_bfloat16, wmma::row_major> vf;
        for (int q = 0; q < nf; ++q) {
            #pragma unroll
            for (int kk = 0; kk < 8; ++kk) {
                wmma::load_matrix_sync(pf, pb + (size_t)fr[q] * 16 * MKV + mc * 128 + kk * 16, MKV);
                wmma::load_matrix_sync(vf, ks + kk * 16 * HDP + fc[q] * 16, HDP);
                wmma::mma_sync(pv[q], pf, vf, pv[q]);
            }
        }
    }
    __syncthreads();
    float* os = sc;   // [32][80] staging
    for (int q = 0; q < nf; ++q)
        wmma::store_matrix_sync(os + fr[q] * 16 * HDP + fc[q] * 16, pv[q], HDP,
                                wmma::mem_row_major);
    __syncthreads();
    // write bf16 directly (same rounding the reference applies)
    for (int i = tid; i < 32 * HD; i += 256) {
        int r = i / HD, d = i % HD;
        out[((size_t)(b * NQ + n0 + r)) * DIM + h * HD + d] =
            __float2bfloat16(os[r * HDP + d]);
    }
}

// ============================================================================
extern "C" void kernel_launch(void* const* d_in, const int* in_sizes, int n_in,
                              void* d_out, int out_size)
{
    (void)in_sizes; (void)n_in; (void)out_size;
    const float* x      = (const float*)d_in[0];
    const float* cond   = (const float*)d_in[1];
    const int*   kvlen  = (const int*)  d_in[2];
    const float* q_w    = (const float*)d_in[3];
    const float* q_b    = (const float*)d_in[4];
    const float* kv_w   = (const float*)d_in[5];
    const float* kv_b   = (const float*)d_in[6];
    const float* proj_w = (const float*)d_in[7];
    const float* proj_b = (const float*)d_in[8];
    const float* qn_w   = (const float*)d_in[9];
    const float* kn_w   = (const float*)d_in[10];
    float* out = (float*)d_out;

    void* p;
    cudaGetSymbolAddress(&p, g_q32);   float* q32 = (float*)p;
    cudaGetSymbolAddress(&p, g_kv32);  float* kv32 = (float*)p;
    cudaGetSymbolAddress(&p, g_q16);   __nv_bfloat16* q16 = (__nv_bfloat16*)p;
    cudaGetSymbolAddress(&p, g_k16);   __nv_bfloat16* k16 = (__nv_bfloat16*)p;
    cudaGetSymbolAddress(&p, g_v16);   __nv_bfloat16* v16 = (__nv_bfloat16*)p;
    cudaGetSymbolAddress(&p, g_att16); __nv_bfloat16* att16 = (__nv_bfloat16*)p;

    cudaFuncSetAttribute(attn_wmma, cudaFuncAttributeMaxDynamicSharedMemorySize,
                         SMEM_ATTN);

    // 1) Q = x @ q_w   (exact fp32)
    gemm_f32<<<dim3(DIM / 128, (BB * NQ) / 128), 256>>>(
        x, q_w, nullptr, q32, BB * NQ, DIM, DIM);
    // 2) KV = cond @ kv_w (exact fp32)
    gemm_f32<<<dim3((2 * DIM) / 128, (BB * MKV) / 128), 256>>>(
        cond, kv_w, nullptr, kv32, BB * MKV, 2 * DIM, DIM);
    // 3) bias + rmsnorm + bf16
    rms_q_kernel<<<(BB * NQ * NH) / 8, 256>>>(q32, q_b, qn_w, q16);
    rms_kv_kernel<<<(BB * MKV * NH) / 8, 256>>>(kv32, kv_b, kn_w, k16, v16);
    // 4) attention — wmma bf16, output stored as bf16 (exact)
    attn_wmma<<<dim3(NQ / 32, NH, BB), 256, SMEM_ATTN>>>(q16, k16, v16, kvlen, att16);
    // 5) out = att @ proj_w + proj_b — bf16x2 tensor-core (A is exactly bf16)
    gemm_out_bf16<<<dim3(DIM / 128, (BB * NQ) / 128), 256>>>(
        att16, proj_w, proj_b, out, BB * NQ, DIM, DIM);
}

// round 10
// speedup vs baseline: 2.2514x; 1.5020x over previous
#include <cuda_runtime.h>
#include <cuda_bf16.h>
#include <mma.h>
#include <cstring>

using namespace nvcuda;

#define BB   4
#define NQ   4096
#define MKV  512
#define DIM  1152
#define NH   16
#define HD   72
#define HDP  80     // head dim padded for 16x16x16 wmma (5 k-steps)

// -------- scratch (static device globals; no allocation) --------
__device__ float          g_q32  [(size_t)BB*NQ*DIM];
__device__ float          g_kv32 [(size_t)BB*MKV*2*DIM];
__device__ __nv_bfloat16  g_q16  [(size_t)BB*NQ*NH*HD];
__device__ __nv_bfloat16  g_k16  [(size_t)BB*NH*MKV*HD];
__device__ __nv_bfloat16  g_v16  [(size_t)BB*NH*MKV*HD];
__device__ __nv_bfloat16  g_att16[(size_t)BB*NQ*DIM];

// ============================================================================
// Exact FP32 GEMM (Q/KV projections). f32x2 packed FMA, double-buffered smem.
// ============================================================================
#define KC  16
#define SLD 132

__device__ __forceinline__ void fma2(unsigned long long& d,
                                     unsigned long long a,
                                     unsigned long long b)
{
    asm("fma.rn.f32x2 %0, %1, %2, %3;" : "=l"(d) : "l"(a), "l"(b), "l"(d));
}
__device__ __forceinline__ unsigned long long pack2(float x)
{
    unsigned long long r;
    asm("mov.b64 %0, {%1, %1};" : "=l"(r) : "f"(x));
    return r;
}

__global__ void __launch_bounds__(256) gemm_f32(
    const float* __restrict__ A, const float* __restrict__ B,
    const float* __restrict__ bias, float* __restrict__ C,
    int M, int N, int K)
{
    __shared__ float As[2][KC][SLD];
    __shared__ float Bs[2][KC][SLD];

    const int tid = threadIdx.x;
    const int tx  = tid & 15;
    const int ty  = tid >> 4;
    const int m0  = blockIdx.y * 128;
    const int n0  = blockIdx.x * 128;

    const int ar = tid >> 2, ac = (tid & 3) * 4;
    const int br = tid >> 5, bc = (tid & 31) * 4;

    unsigned long long acc2[8][4];
    #pragma unroll
    for (int i = 0; i < 8; ++i)
        #pragma unroll
        for (int j = 0; j < 4; ++j) acc2[i][j] = 0ull;

    const int T = K / KC;
    float4 pa0, pa1, pb0, pb1;

    pa0 = *(const float4*)&A[(size_t)(m0 + ar) * K + ac];
    pa1 = *(const float4*)&A[(size_t)(m0 + ar + 64) * K + ac];
    pb0 = *(const float4*)&B[(size_t)br * N + n0 + bc];
    pb1 = *(const float4*)&B[(size_t)(br + 8) * N + n0 + bc];
    {
        As[0][ac + 0][ar] = pa0.x; As[0][ac + 1][ar] = pa0.y;
        As[0][ac + 2][ar] = pa0.z; As[0][ac + 3][ar] = pa0.w;
        As[0][ac + 0][ar + 64] = pa1.x; As[0][ac + 1][ar + 64] = pa1.y;
        As[0][ac + 2][ar + 64] = pa1.z; As[0][ac + 3][ar + 64] = pa1.w;
        *(float4*)&Bs[0][br][bc] = pb0;
        *(float4*)&Bs[0][br + 8][bc] = pb1;
    }
    __syncthreads();

    for (int t = 0; t < T; ++t) {
        const int buf = t & 1;
        if (t + 1 < T) {
            const int kt = (t + 1) * KC;
            pa0 = *(const float4*)&A[(size_t)(m0 + ar) * K + kt + ac];
            pa1 = *(const float4*)&A[(size_t)(m0 + ar + 64) * K + kt + ac];
            pb0 = *(const float4*)&B[(size_t)(kt + br) * N + n0 + bc];
            pb1 = *(const float4*)&B[(size_t)(kt + br + 8) * N + n0 + bc];
        }

        #pragma unroll
        for (int kk = 0; kk < KC; ++kk) {
            float4 av0 = *(const float4*)&As[buf][kk][ty * 8];
            float4 av1 = *(const float4*)&As[buf][kk][ty * 8 + 4];
            float4 bv0 = *(const float4*)&Bs[buf][kk][tx * 8];
            float4 bv1 = *(const float4*)&Bs[buf][kk][tx * 8 + 4];
            unsigned long long b2[4];
            memcpy(&b2[0], &bv0, 16);
            memcpy(&b2[2], &bv1, 16);
            float a[8] = {av0.x, av0.y, av0.z, av0.w, av1.x, av1.y, av1.z, av1.w};
            #pragma unroll
            for (int i = 0; i < 8; ++i) {
                unsigned long long a2 = pack2(a[i]);
                #pragma unroll
                for (int jp = 0; jp < 4; ++jp)
                    fma2(acc2[i][jp], a2, b2[jp]);
            }
        }
        __syncthreads();

        if (t + 1 < T) {
            const int nb = buf ^ 1;
            As[nb][ac + 0][ar] = pa0.x; As[nb][ac + 1][ar] = pa0.y;
            As[nb][ac + 2][ar] = pa0.z; As[nb][ac + 3][ar] = pa0.w;
            As[nb][ac + 0][ar + 64] = pa1.x; As[nb][ac + 1][ar + 64] = pa1.y;
            As[nb][ac + 2][ar + 64] = pa1.z; As[nb][ac + 3][ar + 64] = pa1.w;
            *(float4*)&Bs[nb][br][bc] = pb0;
            *(float4*)&Bs[nb][br + 8][bc] = pb1;
            __syncthreads();
        }
    }

    #pragma unroll
    for (int i = 0; i < 8; ++i) {
        const size_t gm = m0 + ty * 8 + i;
        const int    gn = n0 + tx * 8;
        float o[8];
        memcpy(o, acc2[i], 32);
        if (bias) {
            #pragma unroll
            for (int j = 0; j < 8; ++j) o[j] += bias[gn + j];
        }
        *(float4*)&C[gm * N + gn]     = *(float4*)(o);
        *(float4*)&C[gm * N + gn + 4] = *(float4*)(o + 4);
    }
}

// ============================================================================
// Output projection: bf16x2 tensor-core GEMM (A exactly bf16; B hi/lo split).
// ============================================================================
#define OALD 40
#define OBLD 136

__global__ void __launch_bounds__(256) gemm_out_bf16(
    const __nv_bfloat16* __restrict__ A, const float* __restrict__ B,
    const float* __restrict__ bias, float* __restrict__ C,
    int M, int N, int K)
{
    __shared__ __nv_bfloat16 Asm[128 * OALD];
    __shared__ __nv_bfloat16 Bh [32 * OBLD];
    __shared__ __nv_bfloat16 Bl [32 * OBLD];

    const int tid = threadIdx.x;
    const int wid = tid >> 5;
    const int m0  = blockIdx.y * 128;
    const int n0  = blockIdx.x * 128;
    const int wr  = wid >> 1;
    const int wc  = wid & 1;

    wmma::fragment<wmma::accumulator, 16, 16, 16, float> acc[2][4];
    #pragma unroll
    for (int r = 0; r < 2; ++r)
        #pragma unroll
        for (int c = 0; c < 4; ++c)
            wmma::fill_fragment(acc[r][c], 0.0f);

    const int arow = tid >> 1, acol = (tid & 1) * 16;
    const int brow = tid >> 3, bcol = (tid & 7) * 16;

    for (int kt = 0; kt < K; kt += 32) {
        {
            const __nv_bfloat16* src = &A[(size_t)(m0 + arow) * K + kt + acol];
            *(uint4*)&Asm[arow * OALD + acol]     = *(const uint4*)src;
            *(uint4*)&Asm[arow * OALD + acol + 8] = *(const uint4*)(src + 8);
        }
        {
            const float* src = &B[(size_t)(kt + brow) * N + n0 + bcol];
            #pragma unroll
            for (int q = 0; q < 4; ++q) {
                float4 v = *(const float4*)(src + q * 4);
                #pragma unroll
                for (int e = 0; e < 4; ++e) {
                    float f = (&v.x)[e];
                    __nv_bfloat16 h = __float2bfloat16(f);
                    Bh[brow * OBLD + bcol + q * 4 + e] = h;
                    Bl[brow * OBLD + bcol + q * 4 + e] =
                        __float2bfloat16(f - __bfloat162float(h));
                }
            }
        }
        __syncthreads();

        #pragma unroll
        for (int kk = 0; kk < 32; kk += 16) {
            wmma::fragment<wmma::matrix_a, 16, 16, 16, __nv_bfloat16, wmma::row_major> af[2];
            wmma::fragment<wmma::matrix_b, 16, 16, 16, __nv_bfloat16, wmma::row_major> bhf[4], blf[4];
            #pragma unroll
            for (int r = 0; r < 2; ++r)
                wmma::load_matrix_sync(af[r], Asm + (wr * 32 + r * 16) * OALD + kk, OALD);
            #pragma unroll
            for (int c = 0; c < 4; ++c) {
                wmma::load_matrix_sync(bhf[c], Bh + kk * OBLD + wc * 64 + c * 16, OBLD);
                wmma::load_matrix_sync(blf[c], Bl + kk * OBLD + wc * 64 + c * 16, OBLD);
            }
            #pragma unroll
            for (int r = 0; r < 2; ++r)
                #pragma unroll
                for (int c = 0; c < 4; ++c) {
                    wmma::mma_sync(acc[r][c], af[r], blf[c], acc[r][c]);
                    wmma::mma_sync(acc[r][c], af[r], bhf[c], acc[r][c]);
                }
        }
        __syncthreads();
    }

    #pragma unroll
    for (int r = 0; r < 2; ++r)
        #pragma unroll
        for (int c = 0; c < 4; ++c) {
            const int gm = m0 + wr * 32 + r * 16;
            const int gn = n0 + wc * 64 + c * 16;
            float* tb = (float*)Asm + wid * 16 * 20;
            wmma::store_matrix_sync(tb, acc[r][c], 20, wmma::mem_row_major);
            __syncwarp();
            const int lane = tid & 31;
            #pragma unroll
            for (int e = lane; e < 256; e += 32) {
                int rr = e >> 4, cc = e & 15;
                C[(size_t)(gm + rr) * N + gn + cc] = tb[rr * 20 + cc] + bias[gn + cc];
            }
            __syncwarp();
        }
}

// ============================================================================
// Q path: bias + RMSNorm + bf16 cast. One warp per (b,n,h).
// ============================================================================
__global__ void __launch_bounds__(256) rms_q_kernel(
    const float* __restrict__ q32, const float* __restrict__ qb,
    const float* __restrict__ qw, __nv_bfloat16* __restrict__ q16)
{
    const int wid  = threadIdx.x >> 5;
    const int lane = threadIdx.x & 31;
    const size_t row = (size_t)blockIdx.x * 8 + wid;
    const int h = (int)(row % NH);
    const float* src = q32 + row * HD;

    float v0 = src[lane]      + qb[h * HD + lane];
    float v1 = src[lane + 32] + qb[h * HD + lane + 32];
    float v2 = (lane < 8) ? src[lane + 64] + qb[h * HD + lane + 64] : 0.0f;

    float ss = v0 * v0 + v1 * v1 + v2 * v2;
    #pragma unroll
    for (int o = 16; o; o >>= 1) ss += __shfl_xor_sync(0xffffffffu, ss, o);
    const float inv = 1.0f / sqrtf(ss * (1.0f / 72.0f) + 1e-6f);

    __nv_bfloat16* dst = q16 + row * HD;
    dst[lane]      = __float2bfloat16(v0 * inv * qw[lane]);
    dst[lane + 32] = __float2bfloat16(v1 * inv * qw[lane + 32]);
    if (lane < 8)
        dst[lane + 64] = __float2bfloat16(v2 * inv * qw[lane + 64]);
}

// ============================================================================
// KV path: bias + RMSNorm(k) + cast(v), transpose to [b][h][m][d].
// ============================================================================
__global__ void __launch_bounds__(256) rms_kv_kernel(
    const float* __restrict__ kv32, const float* __restrict__ kvb,
    const float* __restrict__ knw,
    __nv_bfloat16* __restrict__ k16, __nv_bfloat16* __restrict__ v16)
{
    const int wid  = threadIdx.x >> 5;
    const int lane = threadIdx.x & 31;
    const int rid  = blockIdx.x * 8 + wid;
    const int b = rid / (MKV * NH);
    const int m = (rid / NH) % MKV;
    const int h = rid % NH;

    const size_t base = ((size_t)(b * MKV + m) * 2) * DIM + h * HD;
    const float* ksrc = kv32 + base;
    const float* vsrc = kv32 + base + DIM;
    const float* kb   = kvb + h * HD;
    const float* vb   = kvb + DIM + h * HD;
    const size_t obase = ((size_t)(b * NH + h) * MKV + m) * HD;

    float k0 = ksrc[lane]      + kb[lane];
    float k1 = ksrc[lane + 32] + kb[lane + 32];
    float k2 = (lane < 8) ? ksrc[lane + 64] + kb[lane + 64] : 0.0f;
    float ss = k0 * k0 + k1 * k1 + k2 * k2;
    #pragma unroll
    for (int o = 16; o; o >>= 1) ss += __shfl_xor_sync(0xffffffffu, ss, o);
    const float inv = 1.0f / sqrtf(ss * (1.0f / 72.0f) + 1e-6f);
    k16[obase + lane]      = __float2bfloat16(k0 * inv * knw[lane]);
    k16[obase + lane + 32] = __float2bfloat16(k1 * inv * knw[lane + 32]);
    if (lane < 8)
        k16[obase + lane + 64] = __float2bfloat16(k2 * inv * knw[lane + 64]);

    v16[obase + lane]      = __float2bfloat16(vsrc[lane]      + vb[lane]);
    v16[obase + lane + 32] = __float2bfloat16(vsrc[lane + 32] + vb[lane + 32]);
    if (lane < 8)
        v16[obase + lane + 64] = __float2bfloat16(vsrc[lane + 64] + vb[lane + 64]);
}

// ============================================================================
// Two-pass online-softmax attention (flash-lite), ~50KB smem -> 4 blocks/SM.
// Pass A: per 128-KV chunk, wmma scores -> running row max M & rescaled sum S.
// Pass B: recompute chunk scores (L2-hot), probs = bf16(e^{s-M}/S), PV mma.
// No O-fragment rescaling needed (M,S final before PV).
// ============================================================================
#define SCLD 132   // f32 score chunk ld
#define PBLD 136   // bf16 prob chunk ld
#define OFF_QS  0
#define OFF_KS  (OFF_QS + 32*HDP*2)            // 5120
#define OFF_SC  (OFF_KS + 128*HDP*2)           // 25600
#define OFF_PB  (OFF_SC + 32*SCLD*4)           // 42496
#define OFF_M   (OFF_PB + 32*PBLD*2)           // 51200
#define OFF_S   (OFF_M + 32*4)                 // 51328
#define SMEM_ATTN2 (OFF_S + 32*4)              // 51456

__global__ void __launch_bounds__(256) attn_flash(
    const __nv_bfloat16* __restrict__ q16, const __nv_bfloat16* __restrict__ k16,
    const __nv_bfloat16* __restrict__ v16, const int* __restrict__ kvlen_p,
    __nv_bfloat16* __restrict__ out)
{
    extern __shared__ char smem[];
    __nv_bfloat16* qs  = (__nv_bfloat16*)(smem + OFF_QS);   // [32][80]
    __nv_bfloat16* ks  = (__nv_bfloat16*)(smem + OFF_KS);   // [128][80] K then V
    float*         sc  = (float*)(smem + OFF_SC);           // [32][132]
    __nv_bfloat16* pb  = (__nv_bfloat16*)(smem + OFF_PB);   // [32][136]
    float*         rowM = (float*)(smem + OFF_M);
    float*         rowS = (float*)(smem + OFF_S);

    const int tid  = threadIdx.x;
    const int wid  = tid >> 5;
    const int lane = tid & 31;
    const int n0 = blockIdx.x * 32;
    const int h  = blockIdx.y;
    const int b  = blockIdx.z;
    const int kvlen = kvlen_p[b];
    const int nchunks = (kvlen + 127) >> 7;
    const float scale = 0.11785113019775793f;   // 1/sqrt(72)

    // load Q tile (pad cols 72..79 with 0)
    const size_t qbase = (((size_t)(b * NQ + n0)) * NH + h) * HD;
    for (int i = tid; i < 32 * HDP; i += 256) {
        int r = i / HDP, c = i % HDP;
        qs[i] = (c < HD) ? q16[qbase + (size_t)r * NH * HD + c] : __float2bfloat16(0.0f);
    }
    if (tid < 32) { rowM[tid] = -1e30f; rowS[tid] = 0.0f; }

    const size_t kvbase = ((size_t)(b * NH + h)) * MKV * HD;
    const int rt = wid >> 2;    // 0..1 row tile
    const int cp = wid & 3;     // 0..3 col pair

    // ---------------- Pass A: online stats ----------------
    for (int mc = 0; mc < nchunks; ++mc) {
        __syncthreads();
        for (int i = tid; i < 128 * HDP; i += 256) {
            int r = i / HDP, c = i % HDP;
            ks[i] = (c < HD) ? k16[kvbase + (size_t)(mc * 128 + r) * HD + c]
                             : __float2bfloat16(0.0f);
        }
        __syncthreads();
        {
            wmma::fragment<wmma::matrix_a, 16, 16, 16, __nv_bfloat16, wmma::row_major> af;
            wmma::fragment<wmma::matrix_b, 16, 16, 16, __nv_bfloat16, wmma::col_major> bf;
            #pragma unroll
            for (int cc = 0; cc < 2; ++cc) {
                const int ct = cp * 2 + cc;
                wmma::fragment<wmma::accumulator, 16, 16, 16, float> acc;
                wmma::fill_fragment(acc, 0.0f);
                #pragma unroll
                for (int kk = 0; kk < 5; ++kk) {
                    wmma::load_matrix_sync(af, qs + rt * 16 * HDP + kk * 16, HDP);
                    wmma::load_matrix_sync(bf, ks + ct * 16 * HDP + kk * 16, HDP);
                    wmma::mma_sync(acc, af, bf, acc);
                }
                wmma::store_matrix_sync(sc + rt * 16 * SCLD + ct * 16, acc,
                                        SCLD, wmma::mem_row_major);
            }
        }
        __syncthreads();
        const int vmax = min(128, kvlen - mc * 128);
        for (int i = wid; i < 32; i += 8) {
            float* row = sc + i * SCLD;
            float cmax = -1e30f;
            for (int j = lane; j < vmax; j += 32)
                cmax = fmaxf(cmax, row[j] * scale);
            #pragma unroll
            for (int o = 16; o; o >>= 1)
                cmax = fmaxf(cmax, __shfl_xor_sync(0xffffffffu, cmax, o));
            const float m_old = rowM[i];
            const float m_new = fmaxf(m_old, cmax);
            float csum = 0.0f;
            for (int j = lane; j < vmax; j += 32)
                csum += expf(row[j] * scale - m_new);
            #pragma unroll
            for (int o = 16; o; o >>= 1)
                csum += __shfl_xor_sync(0xffffffffu, csum, o);
            if (lane == 0) {
                rowS[i] = rowS[i] * expf(m_old - m_new) + csum;
                rowM[i] = m_new;
            }
        }
    }
    __syncthreads();

    // ---------------- Pass B: probs + PV ----------------
    wmma::fragment<wmma::accumulator, 16, 16, 16, float> pv[2];
    int fr[2], fc[2], nf = 0;
    for (int t = wid; t < 10; t += 8) {
        fr[nf] = t / 5; fc[nf] = t % 5;
        wmma::fill_fragment(pv[nf], 0.0f);
        ++nf;
    }

    for (int mc = 0; mc < nchunks; ++mc) {
        // reload K chunk (L2 hot), recompute scores
        for (int i = tid; i < 128 * HDP; i += 256) {
            int r = i / HDP, c = i % HDP;
            ks[i] = (c < HD) ? k16[kvbase + (size_t)(mc * 128 + r) * HD + c]
                             : __float2bfloat16(0.0f);
        }
        __syncthreads();
        {
            wmma::fragment<wmma::matrix_a, 16, 16, 16, __nv_bfloat16, wmma::row_major> af;
            wmma::fragment<wmma::matrix_b, 16, 16, 16, __nv_bfloat16, wmma::col_major> bf;
            #pragma unroll
            for (int cc = 0; cc < 2; ++cc) {
                const int ct = cp * 2 + cc;
                wmma::fragment<wmma::accumulator, 16, 16, 16, float> acc;
                wmma::fill_fragment(acc, 0.0f);
                #pragma unroll
                for (int kk = 0; kk < 5; ++kk) {
                    wmma::load_matrix_sync(af, qs + rt * 16 * HDP + kk * 16, HDP);
                    wmma::load_matrix_sync(bf, ks + ct * 16 * HDP + kk * 16, HDP);
                    wmma::mma_sync(acc, af, bf, acc);
                }
                wmma::store_matrix_sync(sc + rt * 16 * SCLD + ct * 16, acc,
                                        SCLD, wmma::mem_row_major);
            }
        }
        __syncthreads();
        // probs into pb; load V into ks (scores already consumed from ks)
        const int vmax = min(128, kvlen - mc * 128);
        for (int i = wid; i < 32; i += 8) {
            const float Mi   = rowM[i];
            const float invS = 1.0f / rowS[i];
            const float* row = sc + i * SCLD;
            __nv_bfloat16* prow = pb + i * PBLD;
            for (int j = lane; j < vmax; j += 32)
                prow[j] = __float2bfloat16(expf(row[j] * scale - Mi) * invS);
            for (int j = vmax + lane; j < 128; j += 32)
                prow[j] = __float2bfloat16(0.0f);
        }
        for (int i = tid; i < 128 * HDP; i += 256) {
            int r = i / HDP, c = i % HDP;
            ks[i] = (c < HD) ? v16[kvbase + (size_t)(mc * 128 + r) * HD + c]
                             : __float2bfloat16(0.0f);
        }
        __syncthreads();
        {
            wmma::fragment<wmma::matrix_a, 16, 16, 16, __nv_bfloat16, wmma::row_major> pf;
            wmma::fragment<wmma::matrix_b, 16, 16, 16, __nv_bfloat16, wmma::row_major> vf;
            for (int q = 0; q < nf; ++q) {
                #pragma unroll
                for (int kk = 0; kk < 8; ++kk) {
                    wmma::load_matrix_sync(pf, pb + fr[q] * 16 * PBLD + kk * 16, PBLD);
                    wmma::load_matrix_sync(vf, ks + kk * 16 * HDP + fc[q] * 16, HDP);
                    wmma::mma_sync(pv[q], pf, vf, pv[q]);
                }
            }
        }
        __syncthreads();   // protect ks/sc/pb before next chunk
    }

    // epilogue: stage O via sc as [32][80] f32, emit bf16
    float* os = sc;
    for (int q = 0; q < nf; ++q)
        wmma::store_matrix_sync(os + fr[q] * 16 * HDP + fc[q] * 16, pv[q], HDP,
                                wmma::mem_row_major);
    __syncthreads();
    for (int i = tid; i < 32 * HD; i += 256) {
        int r = i / HD, d = i % HD;
        out[((size_t)(b * NQ + n0 + r)) * DIM + h * HD + d] =
            __float2bfloat16(os[r * HDP + d]);
    }
}

// ============================================================================
extern "C" void kernel_launch(void* const* d_in, const int* in_sizes, int n_in,
                              void* d_out, int out_size)
{
    (void)in_sizes; (void)n_in; (void)out_size;
    const float* x      = (const float*)d_in[0];
    const float* cond   = (const float*)d_in[1];
    const int*   kvlen  = (const int*)  d_in[2];
    const float* q_w    = (const float*)d_in[3];
    const float* q_b    = (const float*)d_in[4];
    const float* kv_w   = (const float*)d_in[5];
    const float* kv_b   = (const float*)d_in[6];
    const float* proj_w = (const float*)d_in[7];
    const float* proj_b = (const float*)d_in[8];
    const float* qn_w   = (const float*)d_in[9];
    const float* kn_w   = (const float*)d_in[10];
    float* out = (float*)d_out;

    void* p;
    cudaGetSymbolAddress(&p, g_q32);   float* q32 = (float*)p;
    cudaGetSymbolAddress(&p, g_kv32);  float* kv32 = (float*)p;
    cudaGetSymbolAddress(&p, g_q16);   __nv_bfloat16* q16 = (__nv_bfloat16*)p;
    cudaGetSymbolAddress(&p, g_k16);   __nv_bfloat16* k16 = (__nv_bfloat16*)p;
    cudaGetSymbolAddress(&p, g_v16);   __nv_bfloat16* v16 = (__nv_bfloat16*)p;
    cudaGetSymbolAddress(&p, g_att16); __nv_bfloat16* att16 = (__nv_bfloat16*)p;

    cudaFuncSetAttribute(attn_flash, cudaFuncAttributeMaxDynamicSharedMemorySize,
                         SMEM_ATTN2);

    // 1) Q = x @ q_w   (exact fp32)
    gemm_f32<<<dim3(DIM / 128, (BB * NQ) / 128), 256>>>(
        x, q_w, nullptr, q32, BB * NQ, DIM, DIM);
    // 2) KV = cond @ kv_w (exact fp32)
    gemm_f32<<<dim3((2 * DIM) / 128, (BB * MKV) / 128), 256>>>(
        cond, kv_w, nullptr, kv32, BB * MKV, 2 * DIM, DIM);
    // 3) bias + rmsnorm + bf16
    rms_q_kernel<<<(BB * NQ * NH) / 8, 256>>>(q32, q_b, qn_w, q16);
    rms_kv_kernel<<<(BB * MKV * NH) / 8, 256>>>(kv32, kv_b, kn_w, k16, v16);
    // 4) attention — two-pass online softmax, 4 blocks/SM
    attn_flash<<<dim3(NQ / 32, NH, BB), 256, SMEM_ATTN2>>>(q16, k16, v16, kvlen, att16);
    // 5) out = att @ proj_w + proj_b — bf16x2 tensor-core
    gemm_out_bf16<<<dim3(DIM / 128, (BB * NQ) / 128), 256>>>(
        att16, proj_w, proj_b, out, BB * NQ, DIM, DIM);
}

// round 11
// speedup vs baseline: 2.3862x; 1.0599x over previous
#include <cuda_runtime.h>
#include <cuda_bf16.h>
#include <mma.h>
#include <cstring>

using namespace nvcuda;

#define BB   4
#define NQ   4096
#define MKV  512
#define DIM  1152
#define NH   16
#define HD   72
#define HDP  80     // head dim padded for 16x16x16 wmma (5 k-steps)
#define QT   64     // queries per attention block

// -------- scratch (static device globals; no allocation) --------
__device__ float          g_q32  [(size_t)BB*NQ*DIM];
__device__ float          g_kv32 [(size_t)BB*MKV*2*DIM];
__device__ __nv_bfloat16  g_q16  [(size_t)BB*NQ*NH*HD];
__device__ __nv_bfloat16  g_k16  [(size_t)BB*NH*MKV*HD];
__device__ __nv_bfloat16  g_v16  [(size_t)BB*NH*MKV*HD];
__device__ __nv_bfloat16  g_att16[(size_t)BB*NQ*DIM];

// ============================================================================
// Exact FP32 GEMM (Q/KV projections). f32x2 packed FMA, double-buffered smem.
// ============================================================================
#define KC  16
#define SLD 132

__device__ __forceinline__ void fma2(unsigned long long& d,
                                     unsigned long long a,
                                     unsigned long long b)
{
    asm("fma.rn.f32x2 %0, %1, %2, %3;" : "=l"(d) : "l"(a), "l"(b), "l"(d));
}
__device__ __forceinline__ unsigned long long pack2(float x)
{
    unsigned long long r;
    asm("mov.b64 %0, {%1, %1};" : "=l"(r) : "f"(x));
    return r;
}

__global__ void __launch_bounds__(256) gemm_f32(
    const float* __restrict__ A, const float* __restrict__ B,
    const float* __restrict__ bias, float* __restrict__ C,
    int M, int N, int K)
{
    __shared__ float As[2][KC][SLD];
    __shared__ float Bs[2][KC][SLD];

    const int tid = threadIdx.x;
    const int tx  = tid & 15;
    const int ty  = tid >> 4;
    const int m0  = blockIdx.y * 128;
    const int n0  = blockIdx.x * 128;

    const int ar = tid >> 2, ac = (tid & 3) * 4;
    const int br = tid >> 5, bc = (tid & 31) * 4;

    unsigned long long acc2[8][4];
    #pragma unroll
    for (int i = 0; i < 8; ++i)
        #pragma unroll
        for (int j = 0; j < 4; ++j) acc2[i][j] = 0ull;

    const int T = K / KC;
    float4 pa0, pa1, pb0, pb1;

    pa0 = *(const float4*)&A[(size_t)(m0 + ar) * K + ac];
    pa1 = *(const float4*)&A[(size_t)(m0 + ar + 64) * K + ac];
    pb0 = *(const float4*)&B[(size_t)br * N + n0 + bc];
    pb1 = *(const float4*)&B[(size_t)(br + 8) * N + n0 + bc];
    {
        As[0][ac + 0][ar] = pa0.x; As[0][ac + 1][ar] = pa0.y;
        As[0][ac + 2][ar] = pa0.z; As[0][ac + 3][ar] = pa0.w;
        As[0][ac + 0][ar + 64] = pa1.x; As[0][ac + 1][ar + 64] = pa1.y;
        As[0][ac + 2][ar + 64] = pa1.z; As[0][ac + 3][ar + 64] = pa1.w;
        *(float4*)&Bs[0][br][bc] = pb0;
        *(float4*)&Bs[0][br + 8][bc] = pb1;
    }
    __syncthreads();

    for (int t = 0; t < T; ++t) {
        const int buf = t & 1;
        if (t + 1 < T) {
            const int kt = (t + 1) * KC;
            pa0 = *(const float4*)&A[(size_t)(m0 + ar) * K + kt + ac];
            pa1 = *(const float4*)&A[(size_t)(m0 + ar + 64) * K + kt + ac];
            pb0 = *(const float4*)&B[(size_t)(kt + br) * N + n0 + bc];
            pb1 = *(const float4*)&B[(size_t)(kt + br + 8) * N + n0 + bc];
        }

        #pragma unroll
        for (int kk = 0; kk < KC; ++kk) {
            float4 av0 = *(const float4*)&As[buf][kk][ty * 8];
            float4 av1 = *(const float4*)&As[buf][kk][ty * 8 + 4];
            float4 bv0 = *(const float4*)&Bs[buf][kk][tx * 8];
            float4 bv1 = *(const float4*)&Bs[buf][kk][tx * 8 + 4];
            unsigned long long b2[4];
            memcpy(&b2[0], &bv0, 16);
            memcpy(&b2[2], &bv1, 16);
            float a[8] = {av0.x, av0.y, av0.z, av0.w, av1.x, av1.y, av1.z, av1.w};
            #pragma unroll
            for (int i = 0; i < 8; ++i) {
                unsigned long long a2 = pack2(a[i]);
                #pragma unroll
                for (int jp = 0; jp < 4; ++jp)
                    fma2(acc2[i][jp], a2, b2[jp]);
            }
        }
        __syncthreads();

        if (t + 1 < T) {
            const int nb = buf ^ 1;
            As[nb][ac + 0][ar] = pa0.x; As[nb][ac + 1][ar] = pa0.y;
            As[nb][ac + 2][ar] = pa0.z; As[nb][ac + 3][ar] = pa0.w;
            As[nb][ac + 0][ar + 64] = pa1.x; As[nb][ac + 1][ar + 64] = pa1.y;
            As[nb][ac + 2][ar + 64] = pa1.z; As[nb][ac + 3][ar + 64] = pa1.w;
            *(float4*)&Bs[nb][br][bc] = pb0;
            *(float4*)&Bs[nb][br + 8][bc] = pb1;
            __syncthreads();
        }
    }

    #pragma unroll
    for (int i = 0; i < 8; ++i) {
        const size_t gm = m0 + ty * 8 + i;
        const int    gn = n0 + tx * 8;
        float o[8];
        memcpy(o, acc2[i], 32);
        if (bias) {
            #pragma unroll
            for (int j = 0; j < 8; ++j) o[j] += bias[gn + j];
        }
        *(float4*)&C[gm * N + gn]     = *(float4*)(o);
        *(float4*)&C[gm * N + gn + 4] = *(float4*)(o + 4);
    }
}

// ============================================================================
// Output projection: bf16x2 tensor-core GEMM (A exactly bf16; B hi/lo split).
// ============================================================================
#define OALD 40
#define OBLD 136

__global__ void __launch_bounds__(256) gemm_out_bf16(
    const __nv_bfloat16* __restrict__ A, const float* __restrict__ B,
    const float* __restrict__ bias, float* __restrict__ C,
    int M, int N, int K)
{
    __shared__ __nv_bfloat16 Asm[128 * OALD];
    __shared__ __nv_bfloat16 Bh [32 * OBLD];
    __shared__ __nv_bfloat16 Bl [32 * OBLD];

    const int tid = threadIdx.x;
    const int wid = tid >> 5;
    const int m0  = blockIdx.y * 128;
    const int n0  = blockIdx.x * 128;
    const int wr  = wid >> 1;
    const int wc  = wid & 1;

    wmma::fragment<wmma::accumulator, 16, 16, 16, float> acc[2][4];
    #pragma unroll
    for (int r = 0; r < 2; ++r)
        #pragma unroll
        for (int c = 0; c < 4; ++c)
            wmma::fill_fragment(acc[r][c], 0.0f);

    const int arow = tid >> 1, acol = (tid & 1) * 16;
    const int brow = tid >> 3, bcol = (tid & 7) * 16;

    for (int kt = 0; kt < K; kt += 32) {
        {
            const __nv_bfloat16* src = &A[(size_t)(m0 + arow) * K + kt + acol];
            *(uint4*)&Asm[arow * OALD + acol]     = *(const uint4*)src;
            *(uint4*)&Asm[arow * OALD + acol + 8] = *(const uint4*)(src + 8);
        }
        {
            const float* src = &B[(size_t)(kt + brow) * N + n0 + bcol];
            #pragma unroll
            for (int q = 0; q < 4; ++q) {
                float4 v = *(const float4*)(src + q * 4);
                #pragma unroll
                for (int e = 0; e < 4; ++e) {
                    float f = (&v.x)[e];
                    __nv_bfloat16 h = __float2bfloat16(f);
                    Bh[brow * OBLD + bcol + q * 4 + e] = h;
                    Bl[brow * OBLD + bcol + q * 4 + e] =
                        __float2bfloat16(f - __bfloat162float(h));
                }
            }
        }
        __syncthreads();

        #pragma unroll
        for (int kk = 0; kk < 32; kk += 16) {
            wmma::fragment<wmma::matrix_a, 16, 16, 16, __nv_bfloat16, wmma::row_major> af[2];
            wmma::fragment<wmma::matrix_b, 16, 16, 16, __nv_bfloat16, wmma::row_major> bhf[4], blf[4];
            #pragma unroll
            for (int r = 0; r < 2; ++r)
                wmma::load_matrix_sync(af[r], Asm + (wr * 32 + r * 16) * OALD + kk, OALD);
            #pragma unroll
            for (int c = 0; c < 4; ++c) {
                wmma::load_matrix_sync(bhf[c], Bh + kk * OBLD + wc * 64 + c * 16, OBLD);
                wmma::load_matrix_sync(blf[c], Bl + kk * OBLD + wc * 64 + c * 16, OBLD);
            }
            #pragma unroll
            for (int r = 0; r < 2; ++r)
                #pragma unroll
                for (int c = 0; c < 4; ++c) {
                    wmma::mma_sync(acc[r][c], af[r], blf[c], acc[r][c]);
                    wmma::mma_sync(acc[r][c], af[r], bhf[c], acc[r][c]);
                }
        }
        __syncthreads();
    }

    #pragma unroll
    for (int r = 0; r < 2; ++r)
        #pragma unroll
        for (int c = 0; c < 4; ++c) {
            const int gm = m0 + wr * 32 + r * 16;
            const int gn = n0 + wc * 64 + c * 16;
            float* tb = (float*)Asm + wid * 16 * 20;
            wmma::store_matrix_sync(tb, acc[r][c], 20, wmma::mem_row_major);
            __syncwarp();
            const int lane = tid & 31;
            #pragma unroll
            for (int e = lane; e < 256; e += 32) {
                int rr = e >> 4, cc = e & 15;
                C[(size_t)(gm + rr) * N + gn + cc] = tb[rr * 20 + cc] + bias[gn + cc];
            }
            __syncwarp();
        }
}

// ============================================================================
// Q path: bias + RMSNorm + bf16 cast. One warp per (b,n,h).
// ============================================================================
__global__ void __launch_bounds__(256) rms_q_kernel(
    const float* __restrict__ q32, const float* __restrict__ qb,
    const float* __restrict__ qw, __nv_bfloat16* __restrict__ q16)
{
    const int wid  = threadIdx.x >> 5;
    const int lane = threadIdx.x & 31;
    const size_t row = (size_t)blockIdx.x * 8 + wid;
    const int h = (int)(row % NH);
    const float* src = q32 + row * HD;

    float v0 = src[lane]      + qb[h * HD + lane];
    float v1 = src[lane + 32] + qb[h * HD + lane + 32];
    float v2 = (lane < 8) ? src[lane + 64] + qb[h * HD + lane + 64] : 0.0f;

    float ss = v0 * v0 + v1 * v1 + v2 * v2;
    #pragma unroll
    for (int o = 16; o; o >>= 1) ss += __shfl_xor_sync(0xffffffffu, ss, o);
    const float inv = 1.0f / sqrtf(ss * (1.0f / 72.0f) + 1e-6f);

    __nv_bfloat16* dst = q16 + row * HD;
    dst[lane]      = __float2bfloat16(v0 * inv * qw[lane]);
    dst[lane + 32] = __float2bfloat16(v1 * inv * qw[lane + 32]);
    if (lane < 8)
        dst[lane + 64] = __float2bfloat16(v2 * inv * qw[lane + 64]);
}

// ============================================================================
// KV path: bias + RMSNorm(k) + cast(v), transpose to [b][h][m][d].
// ============================================================================
__global__ void __launch_bounds__(256) rms_kv_kernel(
    const float* __restrict__ kv32, const float* __restrict__ kvb,
    const float* __restrict__ knw,
    __nv_bfloat16* __restrict__ k16, __nv_bfloat16* __restrict__ v16)
{
    const int wid  = threadIdx.x >> 5;
    const int lane = threadIdx.x & 31;
    const int rid  = blockIdx.x * 8 + wid;
    const int b = rid / (MKV * NH);
    const int m = (rid / NH) % MKV;
    const int h = rid % NH;

    const size_t base = ((size_t)(b * MKV + m) * 2) * DIM + h * HD;
    const float* ksrc = kv32 + base;
    const float* vsrc = kv32 + base + DIM;
    const float* kb   = kvb + h * HD;
    const float* vb   = kvb + DIM + h * HD;
    const size_t obase = ((size_t)(b * NH + h) * MKV + m) * HD;

    float k0 = ksrc[lane]      + kb[lane];
    float k1 = ksrc[lane + 32] + kb[lane + 32];
    float k2 = (lane < 8) ? ksrc[lane + 64] + kb[lane + 64] : 0.0f;
    float ss = k0 * k0 + k1 * k1 + k2 * k2;
    #pragma unroll
    for (int o = 16; o; o >>= 1) ss += __shfl_xor_sync(0xffffffffu, ss, o);
    const float inv = 1.0f / sqrtf(ss * (1.0f / 72.0f) + 1e-6f);
    k16[obase + lane]      = __float2bfloat16(k0 * inv * knw[lane]);
    k16[obase + lane + 32] = __float2bfloat16(k1 * inv * knw[lane + 32]);
    if (lane < 8)
        k16[obase + lane + 64] = __float2bfloat16(k2 * inv * knw[lane + 64]);

    v16[obase + lane]      = __float2bfloat16(vsrc[lane]      + vb[lane]);
    v16[obase + lane + 32] = __float2bfloat16(vsrc[lane + 32] + vb[lane + 32]);
    if (lane < 8)
        v16[obase + lane + 64] = __float2bfloat16(vsrc[lane + 64] + vb[lane + 64]);
}

// ============================================================================
// Two-pass online-softmax attention, QT=64 queries/block, 82KB smem,
// 2 blocks/SM. Same per-row arithmetic as R10 (bit-identical), but KV
// staging traffic per query halved and 2x MMA work per sync.
// ============================================================================
#define SCLD 132   // f32 score chunk ld
#define PBLD 136   // bf16 prob chunk ld
#define OFF_QS  0
#define OFF_KS  (OFF_QS + QT*HDP*2)            // 10240
#define OFF_SC  (OFF_KS + 128*HDP*2)           // 30720
#define OFF_PB  (OFF_SC + QT*SCLD*4)           // 64512
#define OFF_M   (OFF_PB + QT*PBLD*2)           // 81920
#define OFF_S   (OFF_M + QT*4)                 // 82176
#define SMEM_ATTN2 (OFF_S + QT*4)              // 82432

__global__ void __launch_bounds__(256) attn_flash(
    const __nv_bfloat16* __restrict__ q16, const __nv_bfloat16* __restrict__ k16,
    const __nv_bfloat16* __restrict__ v16, const int* __restrict__ kvlen_p,
    __nv_bfloat16* __restrict__ out)
{
    extern __shared__ char smem[];
    __nv_bfloat16* qs  = (__nv_bfloat16*)(smem + OFF_QS);   // [64][80]
    __nv_bfloat16* ks  = (__nv_bfloat16*)(smem + OFF_KS);   // [128][80] K then V
    float*         sc  = (float*)(smem + OFF_SC);           // [64][132]
    __nv_bfloat16* pb  = (__nv_bfloat16*)(smem + OFF_PB);   // [64][136]
    float*         rowM = (float*)(smem + OFF_M);
    float*         rowS = (float*)(smem + OFF_S);

    const int tid  = threadIdx.x;
    const int wid  = tid >> 5;
    const int lane = tid & 31;
    const int n0 = blockIdx.x * QT;
    const int h  = blockIdx.y;
    const int b  = blockIdx.z;
    const int kvlen = kvlen_p[b];
    const int nchunks = (kvlen + 127) >> 7;
    const float scale = 0.11785113019775793f;   // 1/sqrt(72)

    // load Q tile (pad cols 72..79 with 0)
    const size_t qbase = (((size_t)(b * NQ + n0)) * NH + h) * HD;
    for (int i = tid; i < QT * HDP; i += 256) {
        int r = i / HDP, c = i % HDP;
        qs[i] = (c < HD) ? q16[qbase + (size_t)r * NH * HD + c] : __float2bfloat16(0.0f);
    }
    if (tid < QT) { rowM[tid] = -1e30f; rowS[tid] = 0.0f; }

    const size_t kvbase = ((size_t)(b * NH + h)) * MKV * HD;
    const int rt = wid >> 1;    // 0..3 row tile (16 rows each)
    const int cp = wid & 1;     // 0..1 col half (4 col tiles each)

    // ---------------- Pass A: online stats ----------------
    for (int mc = 0; mc < nchunks; ++mc) {
        __syncthreads();
        for (int i = tid; i < 128 * HDP; i += 256) {
            int r = i / HDP, c = i % HDP;
            ks[i] = (c < HD) ? k16[kvbase + (size_t)(mc * 128 + r) * HD + c]
                             : __float2bfloat16(0.0f);
        }
        __syncthreads();
        {
            wmma::fragment<wmma::matrix_a, 16, 16, 16, __nv_bfloat16, wmma::row_major> af;
            wmma::fragment<wmma::matrix_b, 16, 16, 16, __nv_bfloat16, wmma::col_major> bf;
            #pragma unroll
            for (int cc = 0; cc < 4; ++cc) {
                const int ct = cp * 4 + cc;
                wmma::fragment<wmma::accumulator, 16, 16, 16, float> acc;
                wmma::fill_fragment(acc, 0.0f);
                #pragma unroll
                for (int kk = 0; kk < 5; ++kk) {
                    wmma::load_matrix_sync(af, qs + rt * 16 * HDP + kk * 16, HDP);
                    wmma::load_matrix_sync(bf, ks + ct * 16 * HDP + kk * 16, HDP);
                    wmma::mma_sync(acc, af, bf, acc);
                }
                wmma::store_matrix_sync(sc + rt * 16 * SCLD + ct * 16, acc,
                                        SCLD, wmma::mem_row_major);
            }
        }
        __syncthreads();
        const int vmax = min(128, kvlen - mc * 128);
        for (int i = wid; i < QT; i += 8) {
            float* row = sc + i * SCLD;
            float cmax = -1e30f;
            for (int j = lane; j < vmax; j += 32)
                cmax = fmaxf(cmax, row[j] * scale);
            #pragma unroll
            for (int o = 16; o; o >>= 1)
                cmax = fmaxf(cmax, __shfl_xor_sync(0xffffffffu, cmax, o));
            const float m_old = rowM[i];
            const float m_new = fmaxf(m_old, cmax);
            float csum = 0.0f;
            for (int j = lane; j < vmax; j += 32)
                csum += expf(row[j] * scale - m_new);
            #pragma unroll
            for (int o = 16; o; o >>= 1)
                csum += __shfl_xor_sync(0xffffffffu, csum, o);
            if (lane == 0) {
                rowS[i] = rowS[i] * expf(m_old - m_new) + csum;
                rowM[i] = m_new;
            }
        }
    }
    __syncthreads();

    // ---------------- Pass B: probs + PV ----------------
    wmma::fragment<wmma::accumulator, 16, 16, 16, float> pv[3];
    int fr[3], fc[3], nf = 0;
    for (int t = wid; t < 20; t += 8) {    // 4x5 out tiles over 8 warps
        fr[nf] = t / 5; fc[nf] = t % 5;
        wmma::fill_fragment(pv[nf], 0.0f);
        ++nf;
    }

    for (int mc = 0; mc < nchunks; ++mc) {
        // reload K chunk (L2 hot), recompute scores
        for (int i = tid; i < 128 * HDP; i += 256) {
            int r = i / HDP, c = i % HDP;
            ks[i] = (c < HD) ? k16[kvbase + (size_t)(mc * 128 + r) * HD + c]
                             : __float2bfloat16(0.0f);
        }
        __syncthreads();
        {
            wmma::fragment<wmma::matrix_a, 16, 16, 16, __nv_bfloat16, wmma::row_major> af;
            wmma::fragment<wmma::matrix_b, 16, 16, 16, __nv_bfloat16, wmma::col_major> bf;
            #pragma unroll
            for (int cc = 0; cc < 4; ++cc) {
                const int ct = cp * 4 + cc;
                wmma::fragment<wmma::accumulator, 16, 16, 16, float> acc;
                wmma::fill_fragment(acc, 0.0f);
                #pragma unroll
                for (int kk = 0; kk < 5; ++kk) {
                    wmma::load_matrix_sync(af, qs + rt * 16 * HDP + kk * 16, HDP);
                    wmma::load_matrix_sync(bf, ks + ct * 16 * HDP + kk * 16, HDP);
                    wmma::mma_sync(acc, af, bf, acc);
                }
                wmma::store_matrix_sync(sc + rt * 16 * SCLD + ct * 16, acc,
                                        SCLD, wmma::mem_row_major);
            }
        }
        __syncthreads();
        // probs into pb; then V into ks
        const int vmax = min(128, kvlen - mc * 128);
        for (int i = wid; i < QT; i += 8) {
            const float Mi   = rowM[i];
            const float invS = 1.0f / rowS[i];
            const float* row = sc + i * SCLD;
            __nv_bfloat16* prow = pb + i * PBLD;
            for (int j = lane; j < vmax; j += 32)
                prow[j] = __float2bfloat16(expf(row[j] * scale - Mi) * invS);
            for (int j = vmax + lane; j < 128; j += 32)
                prow[j] = __float2bfloat16(0.0f);
        }
        for (int i = tid; i < 128 * HDP; i += 256) {
            int r = i / HDP, c = i % HDP;
            ks[i] = (c < HD) ? v16[kvbase + (size_t)(mc * 128 + r) * HD + c]
                             : __float2bfloat16(0.0f);
        }
        __syncthreads();
        {
            wmma::fragment<wmma::matrix_a, 16, 16, 16, __nv_bfloat16, wmma::row_major> pf;
            wmma::fragment<wmma::matrix_b, 16, 16, 16, __nv_bfloat16, wmma::row_major> vf;
            for (int q = 0; q < nf; ++q) {
                #pragma unroll
                for (int kk = 0; kk < 8; ++kk) {
                    wmma::load_matrix_sync(pf, pb + fr[q] * 16 * PBLD + kk * 16, PBLD);
                    wmma::load_matrix_sync(vf, ks + kk * 16 * HDP + fc[q] * 16, HDP);
                    wmma::mma_sync(pv[q], pf, vf, pv[q]);
                }
            }
        }
        __syncthreads();
    }

    // epilogue: stage O via sc as [64][80] f32, emit bf16
    float* os = sc;
    for (int q = 0; q < nf; ++q)
        wmma::store_matrix_sync(os + fr[q] * 16 * HDP + fc[q] * 16, pv[q], HDP,
                                wmma::mem_row_major);
    __syncthreads();
    for (int i = tid; i < QT * HD; i += 256) {
        int r = i / HD, d = i % HD;
        out[((size_t)(b * NQ + n0 + r)) * DIM + h * HD + d] =
            __float2bfloat16(os[r * HDP + d]);
    }
}

// ============================================================================
extern "C" void kernel_launch(void* const* d_in, const int* in_sizes, int n_in,
                              void* d_out, int out_size)
{
    (void)in_sizes; (void)n_in; (void)out_size;
    const float* x      = (const float*)d_in[0];
    const float* cond   = (const float*)d_in[1];
    const int*   kvlen  = (const int*)  d_in[2];
    const float* q_w    = (const float*)d_in[3];
    const float* q_b    = (const float*)d_in[4];
    const float* kv_w   = (const float*)d_in[5];
    const float* kv_b   = (const float*)d_in[6];
    const float* proj_w = (const float*)d_in[7];
    const float* proj_b = (const float*)d_in[8];
    const float* qn_w   = (const float*)d_in[9];
    const float* kn_w   = (const float*)d_in[10];
    float* out = (float*)d_out;

    void* p;
    cudaGetSymbolAddress(&p, g_q32);   float* q32 = (float*)p;
    cudaGetSymbolAddress(&p, g_kv32);  float* kv32 = (float*)p;
    cudaGetSymbolAddress(&p, g_q16);   __nv_bfloat16* q16 = (__nv_bfloat16*)p;
    cudaGetSymbolAddress(&p, g_k16);   __nv_bfloat16* k16 = (__nv_bfloat16*)p;
    cudaGetSymbolAddress(&p, g_v16);   __nv_bfloat16* v16 = (__nv_bfloat16*)p;
    cudaGetSymbolAddress(&p, g_att16); __nv_bfloat16* att16 = (__nv_bfloat16*)p;

    cudaFuncSetAttribute(attn_flash, cudaFuncAttributeMaxDynamicSharedMemorySize,
                         SMEM_ATTN2);

    // 1) Q = x @ q_w   (exact fp32)
    gemm_f32<<<dim3(DIM / 128, (BB * NQ) / 128), 256>>>(
        x, q_w, nullptr, q32, BB * NQ, DIM, DIM);
    // 2) KV = cond @ kv_w (exact fp32)
    gemm_f32<<<dim3((2 * DIM) / 128, (BB * MKV) / 128), 256>>>(
        cond, kv_w, nullptr, kv32, BB * MKV, 2 * DIM, DIM);
    // 3) bias + rmsnorm + bf16
    rms_q_kernel<<<(BB * NQ * NH) / 8, 256>>>(q32, q_b, qn_w, q16);
    rms_kv_kernel<<<(BB * MKV * NH) / 8, 256>>>(kv32, kv_b, kn_w, k16, v16);
    // 4) attention — two-pass online softmax, 64 queries/block
    attn_flash<<<dim3(NQ / QT, NH, BB), 256, SMEM_ATTN2>>>(q16, k16, v16, kvlen, att16);
    // 5) out = att @ proj_w + proj_b — bf16x2 tensor-core
    gemm_out_bf16<<<dim3(DIM / 128, (BB * NQ) / 128), 256>>>(
        att16, proj_w, proj_b, out, BB * NQ, DIM, DIM);
}